// round 1
// baseline (speedup 1.0000x reference)
#include <cuda_runtime.h>
#include <cuda_bf16.h>
#include <cstdint>

// Problem constants
#define BB   16
#define HH   112
#define WW   112
#define CIN  128
#define FF   256
#define KHH  3
#define KWW  3
#define EE   3
#define OHH  110
#define OWW  110
#define DD   (KHH * KWW * CIN)     // 1152
#define CW   (CIN / 32)            // 4 packed words per pixel
#define NPIX_IN  (BB * HH * WW)    // 200704
#define NPIX_OUT (BB * OHH * OWW)  // 193600
#define KWORDS (FF * EE * KHH * KWW * CW)  // 27648

// Scratch (device globals; no allocation allowed)
__device__ unsigned g_xbits[NPIX_IN * CW];   // packed sign bits of x, [b,h,w][word]
__device__ float    g_S[NPIX_IN];            // per-pixel sum over channels of |x|
__device__ unsigned g_kbits[KWORDS];         // packed kernel sign bits [f][e][tap][word]

// ---------------------------------------------------------------------------
// Pass A: binarize x + channel-abs-sum. One warp per input pixel.
// Layout of x: [B,H,W,CIN] fp32. Bit c of word w set iff x[...,32w+?] >= 0.
// Lane reads 4 consecutive channels (float4), builds a nibble, groups of 8
// lanes assemble one 32-bit word via shfl_xor OR-reduce.
// ---------------------------------------------------------------------------
__global__ __launch_bounds__(256) void binarize_kernel(const float* __restrict__ x) {
    int warp = (blockIdx.x * blockDim.x + threadIdx.x) >> 5;
    int lane = threadIdx.x & 31;
    if (warp >= NPIX_IN) return;

    const float4 v = reinterpret_cast<const float4*>(x + (size_t)warp * CIN)[lane];
    unsigned nib = (v.x >= 0.f ? 1u : 0u)
                 | (v.y >= 0.f ? 2u : 0u)
                 | (v.z >= 0.f ? 4u : 0u)
                 | (v.w >= 0.f ? 8u : 0u);
    float s = fabsf(v.x) + fabsf(v.y) + fabsf(v.z) + fabsf(v.w);

    // assemble word within each group of 8 lanes (covers 32 channels)
    unsigned wv = nib << (4 * (lane & 7));
    wv |= __shfl_xor_sync(0xFFFFFFFFu, wv, 1);
    wv |= __shfl_xor_sync(0xFFFFFFFFu, wv, 2);
    wv |= __shfl_xor_sync(0xFFFFFFFFu, wv, 4);

    // full-warp abs-sum reduce
    #pragma unroll
    for (int off = 16; off > 0; off >>= 1)
        s += __shfl_xor_sync(0xFFFFFFFFu, s, off);

    if ((lane & 7) == 0) g_xbits[warp * CW + (lane >> 3)] = wv;
    if (lane == 0)       g_S[warp] = s;
}

// ---------------------------------------------------------------------------
// Pass B: pack kernel signs. One warp per output word.
// kernels layout: [E,KH,KW,CIN,F] fp32; output word idx = ((f*E+e)*9+tap)*CW+w
// bit (c mod 32) set iff K[e,tap,c,f] >= 0, c = 32w + lane.
// ---------------------------------------------------------------------------
__global__ __launch_bounds__(256) void kpack_kernel(const float* __restrict__ k) {
    int idx  = (blockIdx.x * blockDim.x + threadIdx.x) >> 5;
    int lane = threadIdx.x & 31;
    if (idx >= KWORDS) return;

    int w   = idx & (CW - 1);
    int t3  = idx >> 2;        // /CW
    int tap = t3 % 9;
    int fe  = t3 / 9;
    int e   = fe % EE;
    int f   = fe / EE;
    int c   = w * 32 + lane;

    float val = k[((size_t)(e * 9 + tap) * CIN + c) * FF + f];
    unsigned bits = __ballot_sync(0xFFFFFFFFu, val >= 0.f);
    if (lane == 0) g_kbits[idx] = bits;
}

// ---------------------------------------------------------------------------
// Pass C: main popcount conv. One thread per output pixel (grid-stride),
// all kernel bit-words + alphas staged in shared memory (broadcast reads).
// out[b,i,j,f] = beta * sum_e alpha[e,f] * (D - 2*popc(xwin ^ kbits[e,f]))
// ---------------------------------------------------------------------------
#define SMEM_WORDS (KWORDS + EE * FF)
#define SMEM_BYTES (SMEM_WORDS * 4)

__global__ __launch_bounds__(256) void abc_main_kernel(
    const float* __restrict__ alphas, float* __restrict__ out) {
    extern __shared__ unsigned skb[];
    float* sa = reinterpret_cast<float*>(skb + KWORDS);

    for (int i = threadIdx.x; i < KWORDS; i += blockDim.x) skb[i] = g_kbits[i];
    for (int i = threadIdx.x; i < EE * FF; i += blockDim.x) sa[i] = alphas[i];
    __syncthreads();

    const float inv_d = 1.0f / (float)DD;

    for (int pid = blockIdx.x * blockDim.x + threadIdx.x; pid < NPIX_OUT;
         pid += gridDim.x * blockDim.x) {
        int ow  = pid % OWW;
        int tmp = pid / OWW;
        int oh  = tmp % OHH;
        int b   = tmp / OHH;

        // load 3x3 window of packed bits (9 x uint4) + beta numerator
        uint4 win[9];
        float ssum = 0.f;
        #pragma unroll
        for (int dy = 0; dy < 3; dy++) {
            int row = oh + dy;
            #pragma unroll
            for (int dx = 0; dx < 3; dx++) {
                int p = (b * HH + row) * WW + (ow + dx);
                win[dy * 3 + dx] = reinterpret_cast<const uint4*>(g_xbits)[p];
                ssum += g_S[p];
            }
        }
        float beta = ssum * inv_d;

        size_t obase = (size_t)pid * FF;
        for (int f0 = 0; f0 < FF; f0 += 4) {
            float4 r;
            #pragma unroll
            for (int fi = 0; fi < 4; fi++) {
                int f = f0 + fi;
                const uint4* kb = reinterpret_cast<const uint4*>(skb + f * (EE * 9 * CW));
                int p0 = 0, p1 = 0, p2 = 0;
                #pragma unroll
                for (int t = 0; t < 9; t++) {
                    uint4 xv = win[t];
                    uint4 k0 = kb[t];
                    uint4 k1 = kb[9 + t];
                    uint4 k2 = kb[18 + t];
                    p0 += __popc(xv.x ^ k0.x) + __popc(xv.y ^ k0.y)
                        + __popc(xv.z ^ k0.z) + __popc(xv.w ^ k0.w);
                    p1 += __popc(xv.x ^ k1.x) + __popc(xv.y ^ k1.y)
                        + __popc(xv.z ^ k1.z) + __popc(xv.w ^ k1.w);
                    p2 += __popc(xv.x ^ k2.x) + __popc(xv.y ^ k2.y)
                        + __popc(xv.z ^ k2.z) + __popc(xv.w ^ k2.w);
                }
                float val = sa[f]          * (float)(DD - 2 * p0)
                          + sa[FF + f]     * (float)(DD - 2 * p1)
                          + sa[2 * FF + f] * (float)(DD - 2 * p2);
                (&r.x)[fi] = beta * val;
            }
            *reinterpret_cast<float4*>(out + obase + f0) = r;
        }
    }
}

// ---------------------------------------------------------------------------
extern "C" void kernel_launch(void* const* d_in, const int* in_sizes, int n_in,
                              void* d_out, int out_size) {
    const float* x = (const float*)d_in[0];
    const float* k = (const float*)d_in[1];
    const float* a = (const float*)d_in[2];
    float* out = (float*)d_out;

    // Pass A: 200704 pixels, 8 warps/block
    binarize_kernel<<<NPIX_IN / 8, 256>>>(x);
    // Pass B: 27648 words, 8 warps/block
    kpack_kernel<<<KWORDS / 8, 256>>>(k);
    // Pass C: opt-in to >48KB dynamic smem, then persistent-ish grid
    cudaFuncSetAttribute(abc_main_kernel,
                         cudaFuncAttributeMaxDynamicSharedMemorySize, SMEM_BYTES);
    abc_main_kernel<<<296, 256, SMEM_BYTES>>>(a, out);
}

// round 4
// speedup vs baseline: 5.6790x; 5.6790x over previous
#include <cuda_runtime.h>
#include <cuda_fp16.h>
#include <cstdint>

// ---------------- problem constants ----------------
#define BB 16
#define HH 112
#define WW 112
#define CINC 128
#define FF 256
#define EE 3
#define OH 110
#define OW 110
#define NPIX_IN  (BB * HH * WW)     // 200704
#define NPIX_OUT (BB * OH * OW)     // 193600
#define DD 1152
#define CWRD 4

#if defined(__CUDA_ARCH__) && defined(__CUDA_ARCH_FEAT_SM103_ALL)
#define HAS_TCG 1
#else
#define HAS_TCG 0
#endif

// A row buffer: 112 pixels x 128 ch fp16, blocked SW128 atoms (8 rows x 128B),
// cc-chunk (64ch) stride = 14 atoms * 1024 = 14336B. Total 28672B per image row.
#define RB 28672
// B tile: 32 f x 128 ch fp16, blocked SW128: 4 atom-rows per cc chunk,
// cc stride 4096B. Total 8192B. 9 tiles per f-slice (dx*3+dy).
#define BT 8192

// smem layout (main kernel)
#define SM_TMEM   0
#define SM_BBAR   64
#define SM_FULL(i)  (128 + (i) * 16)
#define SM_EMPTY(i) (192 + (i) * 16)
#define SM_ACC(p)   (256 + (p) * 16)
#define SM_EPI(p)   (288 + (p) * 16)
#define SMEM_A    1024
#define SMEM_B    (SMEM_A + 4 * RB)        // 115712 (1024-aligned)
#define ST_D1     (SMEM_B + 9 * BT)        // 189440
#define ST_D2     (ST_D1 + 512)
#define SMEM_TOT  (ST_D2 + 1024 + 512)     // 191488

// popc fallback smem
#define KWORDS (FF * EE * 9 * CWRD)
#define POPC_SMEM ((KWORDS + EE * FF) * 4)

// idesc: kind::f16 fp16 inputs, fp32 accum, M=128, N=32  (= test_mma's 0x8080490
// minus the bf16 atype/btype bits)
#define MMA_IDESC ((1u << 4) | ((32 / 8) << 17) | ((128 / 16) << 24))

// ---------------- scratch (device globals) ----------------
__device__ __align__(1024) unsigned char g_xq[(size_t)BB * HH * RB + 32768];
__device__ __align__(1024) unsigned char g_w[(size_t)8 * 9 * BT];
__device__ float    g_S[NPIX_IN];
__device__ float    g_beta[NPIX_OUT];
__device__ unsigned g_xbits[NPIX_IN * CWRD];
__device__ unsigned g_kbits[KWORDS];

// ---------------- generic PTX helpers ----------------
__device__ __forceinline__ uint32_t smem_u32(const void* p) {
    uint32_t a;
    asm("{ .reg .u64 t; cvta.to.shared.u64 t, %1; cvt.u32.u64 %0, t; }" : "=r"(a) : "l"(p));
    return a;
}
__device__ __forceinline__ uint32_t elect_one() {
    uint32_t pred;
    asm volatile("{\n\t.reg .pred p;\n\telect.sync _|p, 0xFFFFFFFF;\n\tselp.b32 %0, 1, 0, p;\n\t}" : "=r"(pred));
    return pred;
}
#define MBARRIER_INIT(a, c) \
    asm volatile("mbarrier.init.shared.b64 [%0], %1;" :: "r"((uint32_t)(a)), "r"((uint32_t)(c)) : "memory")
#define MBARRIER_EXPECT_TX(a, b) \
    asm volatile("mbarrier.arrive.expect_tx.shared.b64 _, [%0], %1;" :: "r"((uint32_t)(a)), "r"((uint32_t)(b)) : "memory")
#define MBARRIER_ARRIVE(a) \
    asm volatile("mbarrier.arrive.shared.b64 _, [%0];" :: "r"((uint32_t)(a)) : "memory")
#define MBARRIER_INVAL(a) \
    asm volatile("mbarrier.inval.shared.b64 [%0];" :: "r"((uint32_t)(a)) : "memory")
#define MBARRIER_WAIT(a, par) do {                                           \
    uint32_t _m = (uint32_t)(a); uint32_t _p = (uint32_t)(par);              \
    asm volatile("{\n\t.reg .pred P1;\n\t"                                   \
        "WAIT_LP_%=:\n\t"                                                    \
        "mbarrier.try_wait.parity.acquire.cta.shared::cta.b64 P1, [%0], %1, 0x989680;\n\t" \
        "@P1 bra.uni WAIT_DN_%=;\n\t"                                        \
        "bra.uni WAIT_LP_%=;\n\t"                                            \
        "WAIT_DN_%=:\n\t}" :: "r"(_m), "r"(_p) : "memory");                  \
} while (0)
#define BULK_G2S(dst, src, bytes, mbar) \
    asm volatile("cp.async.bulk.shared::cluster.global.mbarrier::complete_tx::bytes [%0], [%1], %2, [%3];" \
        :: "r"((uint32_t)(dst)), "l"(src), "r"((uint32_t)(bytes)), "r"((uint32_t)(mbar)) : "memory")

// ---------------- tcgen05 helpers (sm_103a only) ----------------
#if HAS_TCG
#define TCGEN05_ALLOC(sa, n) \
    asm volatile("tcgen05.alloc.cta_group::1.sync.aligned.shared::cta.b32 [%0], %1;" \
        :: "r"((uint32_t)(sa)), "r"((uint32_t)(n)) : "memory")
#define TCGEN05_DEALLOC(t, n) \
    asm volatile("tcgen05.dealloc.cta_group::1.sync.aligned.b32 %0, %1;" :: "r"(t), "r"((uint32_t)(n)))
#define TCGEN05_RELINQ() \
    asm volatile("tcgen05.relinquish_alloc_permit.cta_group::1.sync.aligned;")
#define TCGEN05_COMMIT(mb) \
    asm volatile("tcgen05.commit.cta_group::1.mbarrier::arrive::one.shared::cluster.b64 [%0];" \
        :: "r"((uint32_t)(mb)) : "memory")
#define TCGEN05_FENCE_AFTER()  asm volatile("tcgen05.fence::after_thread_sync;" ::: "memory")
#define TCGEN05_FENCE_BEFORE() asm volatile("tcgen05.fence::before_thread_sync;" ::: "memory")
#define TCGEN05_WAIT_LD()      asm volatile("tcgen05.wait::ld.sync.aligned;" ::: "memory")

#define TCGEN05_LD_X32(r, ta)                                                 \
    asm volatile("tcgen05.ld.sync.aligned.32x32b.x32.b32 "                    \
        "{%0, %1, %2, %3, %4, %5, %6, %7, %8, %9, %10, %11, %12, %13, %14, %15, " \
        " %16, %17, %18, %19, %20, %21, %22, %23, %24, %25, %26, %27, %28, %29, %30, %31}, [%32];" \
        : "=r"((r)[0]), "=r"((r)[1]), "=r"((r)[2]), "=r"((r)[3]),             \
          "=r"((r)[4]), "=r"((r)[5]), "=r"((r)[6]), "=r"((r)[7]),             \
          "=r"((r)[8]), "=r"((r)[9]), "=r"((r)[10]), "=r"((r)[11]),           \
          "=r"((r)[12]), "=r"((r)[13]), "=r"((r)[14]), "=r"((r)[15]),         \
          "=r"((r)[16]), "=r"((r)[17]), "=r"((r)[18]), "=r"((r)[19]),         \
          "=r"((r)[20]), "=r"((r)[21]), "=r"((r)[22]), "=r"((r)[23]),         \
          "=r"((r)[24]), "=r"((r)[25]), "=r"((r)[26]), "=r"((r)[27]),         \
          "=r"((r)[28]), "=r"((r)[29]), "=r"((r)[30]), "=r"((r)[31])          \
        : "r"(ta))

__device__ __forceinline__ void mma_f16_ss(uint32_t d, uint64_t adesc, uint64_t bdesc,
                                           uint32_t idesc, uint32_t en) {
    asm volatile(
        "{\n\t.reg .pred p;\n\tsetp.ne.u32 p, %5, 0;\n\t"
        "tcgen05.mma.cta_group::1.kind::f16 [%0], %1, %2, %3, {%4, %4, %4, %4}, p;\n\t}"
        :: "r"(d), "l"(adesc), "l"(bdesc), "r"(idesc), "r"(0u), "r"(en) : "memory");
}

// SW128 K-major descriptor, 1024-aligned bases only (no base_offset games).
__device__ __forceinline__ uint64_t make_desc(uint32_t addr) {
    return (uint64_t(2) << 61) | (uint64_t(1) << 46) | (uint64_t(64) << 32) | (uint64_t(1) << 16)
         | ((uint64_t)((addr >> 4) & 0x3FFF));
}
#endif  // HAS_TCG

// ---------------------------------------------------------------------------
// Prep 1: binarize x; one warp per input pixel. Always computes g_S.
// ---------------------------------------------------------------------------
__global__ __launch_bounds__(256) void binarize_kernel(const float* __restrict__ x) {
    int warp = (blockIdx.x * 256 + threadIdx.x) >> 5;
    int lane = threadIdx.x & 31;
    if (warp >= NPIX_IN) return;

    const float4 v = reinterpret_cast<const float4*>(x + (size_t)warp * CINC)[lane];
    float s = fabsf(v.x) + fabsf(v.y) + fabsf(v.z) + fabsf(v.w);
    #pragma unroll
    for (int off = 16; off > 0; off >>= 1) s += __shfl_xor_sync(0xFFFFFFFFu, s, off);
    if (lane == 0) g_S[warp] = s;

#if HAS_TCG
    unsigned h01 = (v.x >= 0.f ? 0x3C00u : 0xBC00u) | ((v.y >= 0.f ? 0x3C00u : 0xBC00u) << 16);
    unsigned h23 = (v.z >= 0.f ? 0x3C00u : 0xBC00u) | ((v.w >= 0.f ? 0x3C00u : 0xBC00u) << 16);
    int w  = warp % WW;
    int ro = warp / WW;               // b*112 + h
    int c  = lane * 4;                // channel base
    unsigned o = (unsigned)(c >> 6) * 14336 + (unsigned)w * 128 + (c & 63) * 2;
    unsigned swz = o ^ ((o >> 3) & 0x70);
    *reinterpret_cast<uint2*>(g_xq + (size_t)ro * RB + swz) = make_uint2(h01, h23);
#else
    unsigned nib = (v.x >= 0.f ? 1u : 0u) | (v.y >= 0.f ? 2u : 0u)
                 | (v.z >= 0.f ? 4u : 0u) | (v.w >= 0.f ? 8u : 0u);
    unsigned wv = nib << (4 * (lane & 7));
    wv |= __shfl_xor_sync(0xFFFFFFFFu, wv, 1);
    wv |= __shfl_xor_sync(0xFFFFFFFFu, wv, 2);
    wv |= __shfl_xor_sync(0xFFFFFFFFu, wv, 4);
    if ((lane & 7) == 0) g_xbits[warp * CWRD + (lane >> 3)] = wv;
#endif
}

// ---------------------------------------------------------------------------
// Prep 2a (sm_103a): Wc[tap,c,f] = sum_e alpha[e,f]*sign(K[e,tap,c,f]) as one
// fp16 value, laid out as 9 blocked-SW128 B tiles per 32-filter slice.
// ---------------------------------------------------------------------------
__global__ __launch_bounds__(256) void wpack_kernel(const float* __restrict__ k,
                                                    const float* __restrict__ alphas) {
#if HAS_TCG
    int tid = blockIdx.x * 256 + threadIdx.x;
    if (tid >= 9 * CINC * FF) return;
    int f = tid & 255;
    int c = (tid >> 8) & 127;
    int tap = tid >> 15;              // 0..8, = dy*3+dx
    int dy = tap / 3, dx = tap % 3;

    float wc = 0.f;
    #pragma unroll
    for (int e = 0; e < EE; e++) {
        float kv = k[(((size_t)e * 9 + tap) * CINC + c) * FF + f];
        float a  = alphas[e * FF + f];
        wc += (kv >= 0.f) ? a : -a;
    }
    int fs = f >> 5;                  // filter slice
    int p  = f & 31;                  // row within tile
    int tile = dx * 3 + dy;
    unsigned o = (unsigned)(c >> 6) * 4096 + (unsigned)p * 128 + (c & 63) * 2;
    unsigned swz = o ^ ((o >> 3) & 0x70);
    *reinterpret_cast<unsigned short*>(g_w + (size_t)(fs * 9 + tile) * BT + swz) =
        __half_as_ushort(__float2half_rn(wc));
#endif
}

// Prep 2b (fallback): packed kernel sign bits.
__global__ __launch_bounds__(256) void kpack_kernel(const float* __restrict__ k) {
#if !HAS_TCG
    int idx  = (blockIdx.x * blockDim.x + threadIdx.x) >> 5;
    int lane = threadIdx.x & 31;
    if (idx >= KWORDS) return;
    int w   = idx & (CWRD - 1);
    int t3  = idx >> 2;
    int tap = t3 % 9;
    int fe  = t3 / 9;
    int e   = fe % EE;
    int f   = fe / EE;
    int c   = w * 32 + lane;
    float val = k[((size_t)(e * 9 + tap) * CINC + c) * FF + f];
    unsigned bits = __ballot_sync(0xFFFFFFFFu, val >= 0.f);
    if (lane == 0) g_kbits[idx] = bits;
#endif
}

// Prep 3 (sm_103a): beta image.
__global__ __launch_bounds__(256) void beta_kernel() {
#if HAS_TCG
    int pid = blockIdx.x * 256 + threadIdx.x;
    if (pid >= NPIX_OUT) return;
    int ow = pid % OW;
    int t  = pid / OW;
    int oh = t % OH;
    int b  = t / OH;
    float s = 0.f;
    #pragma unroll
    for (int dy = 0; dy < 3; dy++)
        #pragma unroll
        for (int dx = 0; dx < 3; dx++)
            s += g_S[(b * HH + oh + dy) * WW + (ow + dx)];
    g_beta[pid] = s * (1.0f / (float)DD);
#endif
}

// ---------------------------------------------------------------------------
// Main (sm_103a): persistent implicit-GEMM conv, CTA = (batch, 32-filter slice).
// For each output row oh: 3 accumulators D_dx[m=pixel, n=filter] (N=32) from
// UNSHIFTED A rows; tap dx applied by +1/+2 lane shift in the epilogue.
// B (9 tiles, 72KB) resident; A rows stream through 4-slot ring.
// TMEM: ping-pong p = oh&1, D at cols p*96 + dx*32 (192 of 256 cols).
// Warps 0-3 epilogue, 4 producer, 5 MMA.
// ---------------------------------------------------------------------------
__global__ __launch_bounds__(192, 1) void abc_mma2_kernel(float* __restrict__ out) {
#if HAS_TCG
    extern __shared__ char smem[];
    const uint32_t sb = smem_u32(smem);
    const int tid = threadIdx.x;
    const int wid = tid >> 5;
    const int lane = tid & 31;
    const int b  = blockIdx.x >> 3;
    const int fs = blockIdx.x & 7;

    if (tid == 0) {
        MBARRIER_INIT(sb + SM_BBAR, 1);
        #pragma unroll
        for (int i = 0; i < 4; i++) { MBARRIER_INIT(sb + SM_FULL(i), 1); MBARRIER_INIT(sb + SM_EMPTY(i), 1); }
        #pragma unroll
        for (int p = 0; p < 2; p++) { MBARRIER_INIT(sb + SM_ACC(p), 1); MBARRIER_INIT(sb + SM_EPI(p), 4); }
    }
    if (wid == 5) { TCGEN05_ALLOC(sb + SM_TMEM, 256); TCGEN05_RELINQ(); }
    __syncthreads();
    uint32_t tbase;
    asm volatile("ld.shared.b32 %0, [%1];" : "=r"(tbase) : "r"(sb + SM_TMEM));

    // ---------------- producer (warp 4) ----------------
    if (wid == 4) {
        if (elect_one()) {
            MBARRIER_EXPECT_TX(sb + SM_BBAR, 9 * BT);
            #pragma unroll
            for (int t = 0; t < 9; t++)
                BULK_G2S(sb + SMEM_B + t * BT, g_w + (size_t)(fs * 9 + t) * BT, BT, sb + SM_BBAR);
            for (int r = 0; r < HH; r++) {
                int s = r & 3;
                if (r >= 4) MBARRIER_WAIT(sb + SM_EMPTY(s), ((r >> 2) - 1) & 1);
                MBARRIER_EXPECT_TX(sb + SM_FULL(s), RB);
                BULK_G2S(sb + SMEM_A + s * RB, g_xq + (size_t)(b * HH + r) * RB, RB, sb + SM_FULL(s));
            }
        }
    }

    // ---------------- MMA (warp 5) ----------------
    if (wid == 5) {
        // K-step descriptor offsets (16B units): A cc1 at +14336B, B cc1 at +4096B
        const uint32_t akoff[8] = {0, 2, 4, 6, 896, 898, 900, 902};
        const uint32_t bkoff[8] = {0, 2, 4, 6, 256, 258, 260, 262};
        MBARRIER_WAIT(sb + SM_BBAR, 0);
        MBARRIER_WAIT(sb + SM_FULL(0), 0);
        MBARRIER_WAIT(sb + SM_FULL(1), 0);
        for (int oh = 0; oh < OH; oh++) {
            MBARRIER_WAIT(sb + SM_FULL((oh + 2) & 3), ((oh + 2) >> 2) & 1);
            if (oh >= 2) MBARRIER_WAIT(sb + SM_EPI(oh & 1), ((oh >> 1) - 1) & 1);
            TCGEN05_FENCE_AFTER();
            if (elect_one()) {
                int p = oh & 1;
                #pragma unroll
                for (int dx = 0; dx < 3; dx++) {
                    uint32_t dacc = tbase + p * 96 + dx * 32;
                    #pragma unroll
                    for (int dy = 0; dy < 3; dy++) {
                        uint64_t ad = make_desc(sb + SMEM_A + ((oh + dy) & 3) * RB);
                        uint64_t bd = make_desc(sb + SMEM_B + (dx * 3 + dy) * BT);
                        #pragma unroll
                        for (int k = 0; k < 8; k++)
                            mma_f16_ss(dacc, ad + akoff[k], bd + bkoff[k], MMA_IDESC,
                                       !(dy == 0 && k == 0));
                    }
                }
                TCGEN05_COMMIT(sb + SM_EMPTY(oh & 3));
                TCGEN05_COMMIT(sb + SM_ACC(p));
            }
        }
    }

    // ---------------- epilogue (warps 0-3) ----------------
    if (wid < 4) {
        float* sD1 = reinterpret_cast<float*>(smem + ST_D1);
        float* sD2 = reinterpret_cast<float*>(smem + ST_D2);
        for (int oh = 0; oh < OH; oh++) {
            int p = oh & 1;
            MBARRIER_WAIT(sb + SM_ACC(p), (oh >> 1) & 1);
            TCGEN05_FENCE_AFTER();
            uint32_t r0[32], r1[32], r2[32];
            TCGEN05_LD_X32(r0, tbase + p * 96);
            TCGEN05_LD_X32(r1, tbase + p * 96 + 32);
            TCGEN05_LD_X32(r2, tbase + p * 96 + 64);
            TCGEN05_WAIT_LD();
            // stage boundary rows for previous warp
            if (wid > 0 && lane < 2) {
                #pragma unroll
                for (int j = 0; j < 32; j++) {
                    if (lane == 0) sD1[wid * 32 + j] = __uint_as_float(r1[j]);
                    sD2[(wid * 2 + lane) * 32 + j] = __uint_as_float(r2[j]);
                }
            }
            asm volatile("bar.sync 1, 128;" ::: "memory");

            int ow = wid * 32 + lane;
            bool valid = (ow < OW);
            float beta = 0.f;
            int pid = 0;
            if (valid) {
                pid = (b * OH + oh) * OW + ow;
                beta = g_beta[pid];
            }
            float v[32];
            #pragma unroll
            for (int j = 0; j < 32; j++) {
                float f0 = __uint_as_float(r0[j]);
                float f1 = __uint_as_float(__shfl_down_sync(0xFFFFFFFFu, r1[j], 1));
                float f2 = __uint_as_float(__shfl_down_sync(0xFFFFFFFFu, r2[j], 2));
                if (lane == 31 && wid < 3) f1 = sD1[(wid + 1) * 32 + j];
                if (lane >= 30 && wid < 3) f2 = sD2[((wid + 1) * 2 + (lane - 30)) * 32 + j];
                v[j] = beta * (f0 + f1 + f2);
            }
            if (valid) {
                float* ob = out + (size_t)pid * FF + fs * 32;
                #pragma unroll
                for (int q = 0; q < 8; q++)
                    *reinterpret_cast<float4*>(ob + q * 4) =
                        make_float4(v[q * 4], v[q * 4 + 1], v[q * 4 + 2], v[q * 4 + 3]);
            }
            asm volatile("bar.sync 1, 128;" ::: "memory");  // staging reuse guard
            TCGEN05_FENCE_BEFORE();
            if (elect_one()) MBARRIER_ARRIVE(sb + SM_EPI(p));
        }
    }

    __syncthreads();
    if (tid == 0) {
        MBARRIER_INVAL(sb + SM_BBAR);
        #pragma unroll
        for (int i = 0; i < 4; i++) { MBARRIER_INVAL(sb + SM_FULL(i)); MBARRIER_INVAL(sb + SM_EMPTY(i)); }
        #pragma unroll
        for (int p = 0; p < 2; p++) { MBARRIER_INVAL(sb + SM_ACC(p)); MBARRIER_INVAL(sb + SM_EPI(p)); }
    }
    if (wid == 5) TCGEN05_DEALLOC(tbase, 256);
#endif  // HAS_TCG
}

// ---------------------------------------------------------------------------
// Fallback main (non-103a passes): R1 popcount kernel.
// ---------------------------------------------------------------------------
__global__ __launch_bounds__(256) void abc_popc_kernel(
    const float* __restrict__ alphas, float* __restrict__ out) {
#if !HAS_TCG
    extern __shared__ unsigned skb[];
    float* sa = reinterpret_cast<float*>(skb + KWORDS);
    for (int i = threadIdx.x; i < KWORDS; i += blockDim.x) skb[i] = g_kbits[i];
    for (int i = threadIdx.x; i < EE * FF; i += blockDim.x) sa[i] = alphas[i];
    __syncthreads();

    const float inv_d = 1.0f / (float)DD;
    for (int pid = blockIdx.x * blockDim.x + threadIdx.x; pid < NPIX_OUT;
         pid += gridDim.x * blockDim.x) {
        int ow  = pid % OW;
        int tmp = pid / OW;
        int oh  = tmp % OH;
        int b   = tmp / OH;
        uint4 win[9];
        float ssum = 0.f;
        #pragma unroll
        for (int dy = 0; dy < 3; dy++)
            #pragma unroll
            for (int dx = 0; dx < 3; dx++) {
                int p = (b * HH + oh + dy) * WW + (ow + dx);
                win[dy * 3 + dx] = reinterpret_cast<const uint4*>(g_xbits)[p];
                ssum += g_S[p];
            }
        float beta = ssum * inv_d;
        size_t obase = (size_t)pid * FF;
        for (int f0 = 0; f0 < FF; f0 += 4) {
            float4 r;
            #pragma unroll
            for (int fi = 0; fi < 4; fi++) {
                int f = f0 + fi;
                const uint4* kb = reinterpret_cast<const uint4*>(skb + f * (EE * 9 * CWRD));
                int p0 = 0, p1 = 0, p2 = 0;
                #pragma unroll
                for (int t = 0; t < 9; t++) {
                    uint4 xv = win[t];
                    uint4 k0 = kb[t], k1 = kb[9 + t], k2 = kb[18 + t];
                    p0 += __popc(xv.x ^ k0.x) + __popc(xv.y ^ k0.y) + __popc(xv.z ^ k0.z) + __popc(xv.w ^ k0.w);
                    p1 += __popc(xv.x ^ k1.x) + __popc(xv.y ^ k1.y) + __popc(xv.z ^ k1.z) + __popc(xv.w ^ k1.w);
                    p2 += __popc(xv.x ^ k2.x) + __popc(xv.y ^ k2.y) + __popc(xv.z ^ k2.z) + __popc(xv.w ^ k2.w);
                }
                float val = sa[f] * (float)(DD - 2 * p0) + sa[FF + f] * (float)(DD - 2 * p1)
                          + sa[2 * FF + f] * (float)(DD - 2 * p2);
                (&r.x)[fi] = beta * val;
            }
            *reinterpret_cast<float4*>(out + obase + f0) = r;
        }
    }
#endif  // !HAS_TCG
}

// ---------------------------------------------------------------------------
extern "C" void kernel_launch(void* const* d_in, const int* in_sizes, int n_in,
                              void* d_out, int out_size) {
    const float* x = (const float*)d_in[0];
    const float* k = (const float*)d_in[1];
    const float* a = (const float*)d_in[2];
    float* out = (float*)d_out;

    binarize_kernel<<<NPIX_IN / 8, 256>>>(x);
    wpack_kernel<<<(9 * CINC * FF) / 256, 256>>>(k, a);
    kpack_kernel<<<KWORDS / 8, 256>>>(k);
    beta_kernel<<<(NPIX_OUT + 255) / 256, 256>>>();

    cudaFuncSetAttribute(abc_mma2_kernel,
                         cudaFuncAttributeMaxDynamicSharedMemorySize, SMEM_TOT);
    cudaFuncSetAttribute(abc_popc_kernel,
                         cudaFuncAttributeMaxDynamicSharedMemorySize, POPC_SMEM);
    abc_mma2_kernel<<<BB * 8, 192, SMEM_TOT>>>(out);
    abc_popc_kernel<<<296, 256, POPC_SMEM>>>(a, out);
}

// round 5
// speedup vs baseline: 5.8168x; 1.0242x over previous
#include <cuda_runtime.h>
#include <cuda_fp16.h>
#include <cstdint>

// ---------------- problem constants ----------------
#define BB 16
#define HH 112
#define WW 112
#define CINC 128
#define FF 256
#define EE 3
#define OH 110
#define OW 110
#define NPIX_IN  (BB * HH * WW)     // 200704
#define NPIX_OUT (BB * OH * OW)     // 193600
#define DD 1152
#define CWRD 4

#if defined(__CUDA_ARCH__) && defined(__CUDA_ARCH_FEAT_SM103_ALL)
#define HAS_TCG 1
#else
#define HAS_TCG 0
#endif

// A row buffer: 112 px x 128 ch fp16, blocked SW128 atoms, cc stride 14336B.
#define RB 28672
// B tile: 32 f x 128 ch fp16, blocked SW128, cc stride 4096B.
#define BT 8192

// smem layout (main kernel)
#define SM_TMEM   0
#define SM_BBAR   64
#define SM_FULL(i)  (128 + (i) * 16)
#define SM_EMPTY(i) (192 + (i) * 16)
#define SM_ACC(p)   (256 + (p) * 16)
#define SM_EPI(p)   (320 + (p) * 16)
#define SMEM_A    1024
#define SMEM_B    (SMEM_A + 4 * RB)        // 115712
#define ST_D1     (SMEM_B + 9 * BT)        // 189440
#define ST_D2     (ST_D1 + 2 * 128 * 4)    // 190464
#define SMEM_TOT  (ST_D2 + 2 * 256 * 4 + 64)  // 192576

// popc fallback smem
#define KWORDS (FF * EE * 9 * CWRD)
#define POPC_SMEM ((KWORDS + EE * FF) * 4)

// idesc: kind::f16 fp16 inputs, fp32 accum, M=128, N=32
#define MMA_IDESC ((1u << 4) | ((32 / 8) << 17) | ((128 / 16) << 24))

// ---------------- scratch (device globals) ----------------
__device__ __align__(1024) unsigned char g_xq[(size_t)BB * HH * RB + 32768];
__device__ __align__(1024) unsigned char g_w[(size_t)8 * 9 * BT];
__device__ float    g_S[NPIX_IN];
__device__ float    g_beta[NPIX_OUT];
__device__ unsigned g_xbits[NPIX_IN * CWRD];
__device__ unsigned g_kbits[KWORDS];

// ---------------- generic PTX helpers ----------------
__device__ __forceinline__ uint32_t smem_u32(const void* p) {
    uint32_t a;
    asm("{ .reg .u64 t; cvta.to.shared.u64 t, %1; cvt.u32.u64 %0, t; }" : "=r"(a) : "l"(p));
    return a;
}
__device__ __forceinline__ uint32_t elect_one() {
    uint32_t pred;
    asm volatile("{\n\t.reg .pred p;\n\telect.sync _|p, 0xFFFFFFFF;\n\tselp.b32 %0, 1, 0, p;\n\t}" : "=r"(pred));
    return pred;
}
#define MBARRIER_INIT(a, c) \
    asm volatile("mbarrier.init.shared.b64 [%0], %1;" :: "r"((uint32_t)(a)), "r"((uint32_t)(c)) : "memory")
#define MBARRIER_EXPECT_TX(a, b) \
    asm volatile("mbarrier.arrive.expect_tx.shared.b64 _, [%0], %1;" :: "r"((uint32_t)(a)), "r"((uint32_t)(b)) : "memory")
#define MBARRIER_ARRIVE(a) \
    asm volatile("mbarrier.arrive.shared.b64 _, [%0];" :: "r"((uint32_t)(a)) : "memory")
#define MBARRIER_INVAL(a) \
    asm volatile("mbarrier.inval.shared.b64 [%0];" :: "r"((uint32_t)(a)) : "memory")
#define MBARRIER_WAIT(a, par) do {                                           \
    uint32_t _m = (uint32_t)(a); uint32_t _p = (uint32_t)(par);              \
    asm volatile("{\n\t.reg .pred P1;\n\t"                                   \
        "WAIT_LP_%=:\n\t"                                                    \
        "mbarrier.try_wait.parity.acquire.cta.shared::cta.b64 P1, [%0], %1, 0x989680;\n\t" \
        "@P1 bra.uni WAIT_DN_%=;\n\t"                                        \
        "bra.uni WAIT_LP_%=;\n\t"                                            \
        "WAIT_DN_%=:\n\t}" :: "r"(_m), "r"(_p) : "memory");                  \
} while (0)
#define BULK_G2S(dst, src, bytes, mbar) \
    asm volatile("cp.async.bulk.shared::cluster.global.mbarrier::complete_tx::bytes [%0], [%1], %2, [%3];" \
        :: "r"((uint32_t)(dst)), "l"(src), "r"((uint32_t)(bytes)), "r"((uint32_t)(mbar)) : "memory")

// ---------------- tcgen05 helpers (sm_103a only) ----------------
#if HAS_TCG
#define TCGEN05_ALLOC(sa, n) \
    asm volatile("tcgen05.alloc.cta_group::1.sync.aligned.shared::cta.b32 [%0], %1;" \
        :: "r"((uint32_t)(sa)), "r"((uint32_t)(n)) : "memory")
#define TCGEN05_DEALLOC(t, n) \
    asm volatile("tcgen05.dealloc.cta_group::1.sync.aligned.b32 %0, %1;" :: "r"(t), "r"((uint32_t)(n)))
#define TCGEN05_RELINQ() \
    asm volatile("tcgen05.relinquish_alloc_permit.cta_group::1.sync.aligned;")
#define TCGEN05_COMMIT(mb) \
    asm volatile("tcgen05.commit.cta_group::1.mbarrier::arrive::one.shared::cluster.b64 [%0];" \
        :: "r"((uint32_t)(mb)) : "memory")
#define TCGEN05_FENCE_AFTER()  asm volatile("tcgen05.fence::after_thread_sync;" ::: "memory")
#define TCGEN05_FENCE_BEFORE() asm volatile("tcgen05.fence::before_thread_sync;" ::: "memory")
#define TCGEN05_WAIT_LD()      asm volatile("tcgen05.wait::ld.sync.aligned;" ::: "memory")

#define TCGEN05_LD_X32(r, ta)                                                 \
    asm volatile("tcgen05.ld.sync.aligned.32x32b.x32.b32 "                    \
        "{%0, %1, %2, %3, %4, %5, %6, %7, %8, %9, %10, %11, %12, %13, %14, %15, " \
        " %16, %17, %18, %19, %20, %21, %22, %23, %24, %25, %26, %27, %28, %29, %30, %31}, [%32];" \
        : "=r"((r)[0]), "=r"((r)[1]), "=r"((r)[2]), "=r"((r)[3]),             \
          "=r"((r)[4]), "=r"((r)[5]), "=r"((r)[6]), "=r"((r)[7]),             \
          "=r"((r)[8]), "=r"((r)[9]), "=r"((r)[10]), "=r"((r)[11]),           \
          "=r"((r)[12]), "=r"((r)[13]), "=r"((r)[14]), "=r"((r)[15]),         \
          "=r"((r)[16]), "=r"((r)[17]), "=r"((r)[18]), "=r"((r)[19]),         \
          "=r"((r)[20]), "=r"((r)[21]), "=r"((r)[22]), "=r"((r)[23]),         \
          "=r"((r)[24]), "=r"((r)[25]), "=r"((r)[26]), "=r"((r)[27]),         \
          "=r"((r)[28]), "=r"((r)[29]), "=r"((r)[30]), "=r"((r)[31])          \
        : "r"(ta))

__device__ __forceinline__ void mma_f16_ss(uint32_t d, uint64_t adesc, uint64_t bdesc,
                                           uint32_t idesc, uint32_t en) {
    asm volatile(
        "{\n\t.reg .pred p;\n\tsetp.ne.u32 p, %5, 0;\n\t"
        "tcgen05.mma.cta_group::1.kind::f16 [%0], %1, %2, %3, {%4, %4, %4, %4}, p;\n\t}"
        :: "r"(d), "l"(adesc), "l"(bdesc), "r"(idesc), "r"(0u), "r"(en) : "memory");
}

// SW128 K-major descriptor, 1024-aligned bases only.
__device__ __forceinline__ uint64_t make_desc(uint32_t addr) {
    return (uint64_t(2) << 61) | (uint64_t(1) << 46) | (uint64_t(64) << 32) | (uint64_t(1) << 16)
         | ((uint64_t)((addr >> 4) & 0x3FFF));
}
#endif  // HAS_TCG

// ---------------------------------------------------------------------------
// Prep 1: binarize x; one warp per input pixel. Always computes g_S.
// ---------------------------------------------------------------------------
__global__ __launch_bounds__(256) void binarize_kernel(const float* __restrict__ x) {
    int warp = (blockIdx.x * 256 + threadIdx.x) >> 5;
    int lane = threadIdx.x & 31;
    if (warp >= NPIX_IN) return;

    const float4 v = reinterpret_cast<const float4*>(x + (size_t)warp * CINC)[lane];
    float s = fabsf(v.x) + fabsf(v.y) + fabsf(v.z) + fabsf(v.w);
    #pragma unroll
    for (int off = 16; off > 0; off >>= 1) s += __shfl_xor_sync(0xFFFFFFFFu, s, off);
    if (lane == 0) g_S[warp] = s;

#if HAS_TCG
    unsigned h01 = (v.x >= 0.f ? 0x3C00u : 0xBC00u) | ((v.y >= 0.f ? 0x3C00u : 0xBC00u) << 16);
    unsigned h23 = (v.z >= 0.f ? 0x3C00u : 0xBC00u) | ((v.w >= 0.f ? 0x3C00u : 0xBC00u) << 16);
    int w  = warp % WW;
    int ro = warp / WW;               // b*112 + h
    int c  = lane * 4;                // channel base
    unsigned o = (unsigned)(c >> 6) * 14336 + (unsigned)w * 128 + (c & 63) * 2;
    unsigned swz = o ^ ((o >> 3) & 0x70);
    *reinterpret_cast<uint2*>(g_xq + (size_t)ro * RB + swz) = make_uint2(h01, h23);
#else
    unsigned nib = (v.x >= 0.f ? 1u : 0u) | (v.y >= 0.f ? 2u : 0u)
                 | (v.z >= 0.f ? 4u : 0u) | (v.w >= 0.f ? 8u : 0u);
    unsigned wv = nib << (4 * (lane & 7));
    wv |= __shfl_xor_sync(0xFFFFFFFFu, wv, 1);
    wv |= __shfl_xor_sync(0xFFFFFFFFu, wv, 2);
    wv |= __shfl_xor_sync(0xFFFFFFFFu, wv, 4);
    if ((lane & 7) == 0) g_xbits[warp * CWRD + (lane >> 3)] = wv;
#endif
}

// ---------------------------------------------------------------------------
// Prep 2a (sm_103a): Wc[tap,c,f] = sum_e alpha[e,f]*sign(K[e,tap,c,f]), fp16,
// laid out as 9 blocked-SW128 B tiles per 32-filter slice.
// ---------------------------------------------------------------------------
__global__ __launch_bounds__(256) void wpack_kernel(const float* __restrict__ k,
                                                    const float* __restrict__ alphas) {
#if HAS_TCG
    int tid = blockIdx.x * 256 + threadIdx.x;
    if (tid >= 9 * CINC * FF) return;
    int f = tid & 255;
    int c = (tid >> 8) & 127;
    int tap = tid >> 15;              // 0..8, = dy*3+dx
    int dy = tap / 3, dx = tap % 3;

    float wc = 0.f;
    #pragma unroll
    for (int e = 0; e < EE; e++) {
        float kv = k[(((size_t)e * 9 + tap) * CINC + c) * FF + f];
        float a  = alphas[e * FF + f];
        wc += (kv >= 0.f) ? a : -a;
    }
    int fs = f >> 5;
    int p  = f & 31;
    int tile = dx * 3 + dy;
    unsigned o = (unsigned)(c >> 6) * 4096 + (unsigned)p * 128 + (c & 63) * 2;
    unsigned swz = o ^ ((o >> 3) & 0x70);
    *reinterpret_cast<unsigned short*>(g_w + (size_t)(fs * 9 + tile) * BT + swz) =
        __half_as_ushort(__float2half_rn(wc));
#endif
}

// Prep 2b (fallback): packed kernel sign bits.
__global__ __launch_bounds__(256) void kpack_kernel(const float* __restrict__ k) {
#if !HAS_TCG
    int idx  = (blockIdx.x * blockDim.x + threadIdx.x) >> 5;
    int lane = threadIdx.x & 31;
    if (idx >= KWORDS) return;
    int w   = idx & (CWRD - 1);
    int t3  = idx >> 2;
    int tap = t3 % 9;
    int fe  = t3 / 9;
    int e   = fe % EE;
    int f   = fe / EE;
    int c   = w * 32 + lane;
    float val = k[((size_t)(e * 9 + tap) * CINC + c) * FF + f];
    unsigned bits = __ballot_sync(0xFFFFFFFFu, val >= 0.f);
    if (lane == 0) g_kbits[idx] = bits;
#endif
}

// Prep 3 (sm_103a): beta image.
__global__ __launch_bounds__(256) void beta_kernel() {
#if HAS_TCG
    int pid = blockIdx.x * 256 + threadIdx.x;
    if (pid >= NPIX_OUT) return;
    int ow = pid % OW;
    int t  = pid / OW;
    int oh = t % OH;
    int b  = t / OH;
    float s = 0.f;
    #pragma unroll
    for (int dy = 0; dy < 3; dy++)
        #pragma unroll
        for (int dx = 0; dx < 3; dx++)
            s += g_S[(b * HH + oh + dy) * WW + (ow + dx)];
    g_beta[pid] = s * (1.0f / (float)DD);
#endif
}

// ---------------------------------------------------------------------------
// Main (sm_103a): persistent implicit-GEMM conv, CTA = (batch, 32-filter slice).
// Per output row: 3 accumulators D_dx (N=32) from UNSHIFTED A rows; dx applied
// by lane shift in the epilogue. B resident (72KB); A rows in 4-slot ring.
// TMEM: 4-deep pipeline p = oh&3, D at cols p*128 + dx*32 (384 of 512).
// Warps 0-3 epilogue, 4 producer, 5 MMA.
// ---------------------------------------------------------------------------
__global__ __launch_bounds__(192, 1) void abc_mma2_kernel(float* __restrict__ out) {
#if HAS_TCG
    extern __shared__ char smem[];
    const uint32_t sb = smem_u32(smem);
    const int tid = threadIdx.x;
    const int wid = tid >> 5;
    const int lane = tid & 31;
    const int b  = blockIdx.x >> 3;
    const int fs = blockIdx.x & 7;

    if (tid == 0) {
        MBARRIER_INIT(sb + SM_BBAR, 1);
        #pragma unroll
        for (int i = 0; i < 4; i++) {
            MBARRIER_INIT(sb + SM_FULL(i), 1);
            MBARRIER_INIT(sb + SM_EMPTY(i), 1);
            MBARRIER_INIT(sb + SM_ACC(i), 1);
            MBARRIER_INIT(sb + SM_EPI(i), 4);
        }
    }
    if (wid == 5) { TCGEN05_ALLOC(sb + SM_TMEM, 512); TCGEN05_RELINQ(); }
    __syncthreads();
    uint32_t tbase;
    asm volatile("ld.shared.b32 %0, [%1];" : "=r"(tbase) : "r"(sb + SM_TMEM));

    // ---------------- producer (warp 4) ----------------
    if (wid == 4) {
        if (elect_one()) {
            MBARRIER_EXPECT_TX(sb + SM_BBAR, 9 * BT);
            #pragma unroll
            for (int t = 0; t < 9; t++)
                BULK_G2S(sb + SMEM_B + t * BT, g_w + (size_t)(fs * 9 + t) * BT, BT, sb + SM_BBAR);
            for (int r = 0; r < HH; r++) {
                int s = r & 3;
                if (r >= 4) MBARRIER_WAIT(sb + SM_EMPTY(s), ((r >> 2) - 1) & 1);
                MBARRIER_EXPECT_TX(sb + SM_FULL(s), RB);
                BULK_G2S(sb + SMEM_A + s * RB, g_xq + (size_t)(b * HH + r) * RB, RB, sb + SM_FULL(s));
            }
        }
    }

    // ---------------- MMA (warp 5) ----------------
    if (wid == 5) {
        // K-step descriptor offsets (16B units): A cc1 at +14336B, B cc1 at +4096B
        const uint32_t akoff[8] = {0, 2, 4, 6, 896, 898, 900, 902};
        const uint32_t bkoff[8] = {0, 2, 4, 6, 256, 258, 260, 262};
        MBARRIER_WAIT(sb + SM_BBAR, 0);
        MBARRIER_WAIT(sb + SM_FULL(0), 0);
        MBARRIER_WAIT(sb + SM_FULL(1), 0);
        for (int oh = 0; oh < OH; oh++) {
            MBARRIER_WAIT(sb + SM_FULL((oh + 2) & 3), ((oh + 2) >> 2) & 1);
            if (oh >= 4) MBARRIER_WAIT(sb + SM_EPI(oh & 3), ((oh >> 2) - 1) & 1);
            TCGEN05_FENCE_AFTER();
            if (elect_one()) {
                int p = oh & 3;
                #pragma unroll
                for (int dx = 0; dx < 3; dx++) {
                    uint32_t dacc = tbase + p * 128 + dx * 32;
                    #pragma unroll
                    for (int dy = 0; dy < 3; dy++) {
                        uint64_t ad = make_desc(sb + SMEM_A + ((oh + dy) & 3) * RB);
                        uint64_t bd = make_desc(sb + SMEM_B + (dx * 3 + dy) * BT);
                        #pragma unroll
                        for (int k = 0; k < 8; k++)
                            mma_f16_ss(dacc, ad + akoff[k], bd + bkoff[k], MMA_IDESC,
                                       !(dy == 0 && k == 0));
                    }
                }
                TCGEN05_COMMIT(sb + SM_EMPTY(oh & 3));
                TCGEN05_COMMIT(sb + SM_ACC(p));
            }
        }
    }

    // ---------------- epilogue (warps 0-3) ----------------
    if (wid < 4) {
        float* sD1 = reinterpret_cast<float*>(smem + ST_D1);
        float* sD2 = reinterpret_cast<float*>(smem + ST_D2);
        for (int oh = 0; oh < OH; oh++) {
            int p  = oh & 3;
            int p2 = oh & 1;
            MBARRIER_WAIT(sb + SM_ACC(p), (oh >> 2) & 1);
            TCGEN05_FENCE_AFTER();
            uint32_t r0[32], r1[32], r2[32];
            TCGEN05_LD_X32(r0, tbase + p * 128);
            TCGEN05_LD_X32(r1, tbase + p * 128 + 32);
            TCGEN05_LD_X32(r2, tbase + p * 128 + 64);
            TCGEN05_WAIT_LD();
            TCGEN05_FENCE_BEFORE();
            if (elect_one()) MBARRIER_ARRIVE(sb + SM_EPI(p));  // free accumulator early

            // stage boundary rows for previous warp (double-buffered by oh&1)
            if (wid > 0 && lane < 2) {
                #pragma unroll
                for (int j = 0; j < 32; j++) {
                    if (lane == 0) sD1[p2 * 128 + wid * 32 + j] = __uint_as_float(r1[j]);
                    sD2[p2 * 256 + (wid * 2 + lane) * 32 + j] = __uint_as_float(r2[j]);
                }
            }
            asm volatile("bar.sync 1, 128;" ::: "memory");

            int ow = wid * 32 + lane;
            bool valid = (ow < OW);
            float beta = 0.f;
            int pid = 0;
            if (valid) {
                pid = (b * OH + oh) * OW + ow;
                beta = g_beta[pid];
            }
            float v[32];
            #pragma unroll
            for (int j = 0; j < 32; j++) {
                float f0 = __uint_as_float(r0[j]);
                float f1 = __uint_as_float(__shfl_down_sync(0xFFFFFFFFu, r1[j], 1));
                float f2 = __uint_as_float(__shfl_down_sync(0xFFFFFFFFu, r2[j], 2));
                if (lane == 31 && wid < 3) f1 = sD1[p2 * 128 + (wid + 1) * 32 + j];
                if (lane >= 30 && wid < 3) f2 = sD2[p2 * 256 + ((wid + 1) * 2 + (lane - 30)) * 32 + j];
                v[j] = beta * (f0 + f1 + f2);
            }
            if (valid) {
                float* ob = out + (size_t)pid * FF + fs * 32;
                #pragma unroll
                for (int q = 0; q < 8; q++)
                    *reinterpret_cast<float4*>(ob + q * 4) =
                        make_float4(v[q * 4], v[q * 4 + 1], v[q * 4 + 2], v[q * 4 + 3]);
            }
        }
    }

    __syncthreads();
    if (tid == 0) {
        MBARRIER_INVAL(sb + SM_BBAR);
        #pragma unroll
        for (int i = 0; i < 4; i++) {
            MBARRIER_INVAL(sb + SM_FULL(i)); MBARRIER_INVAL(sb + SM_EMPTY(i));
            MBARRIER_INVAL(sb + SM_ACC(i));  MBARRIER_INVAL(sb + SM_EPI(i));
        }
    }
    if (wid == 5) TCGEN05_DEALLOC(tbase, 512);
#endif  // HAS_TCG
}

// ---------------------------------------------------------------------------
// Fallback main (non-103a passes): R1 popcount kernel.
// ---------------------------------------------------------------------------
__global__ __launch_bounds__(256) void abc_popc_kernel(
    const float* __restrict__ alphas, float* __restrict__ out) {
#if !HAS_TCG
    extern __shared__ unsigned skb[];
    float* sa = reinterpret_cast<float*>(skb + KWORDS);
    for (int i = threadIdx.x; i < KWORDS; i += blockDim.x) skb[i] = g_kbits[i];
    for (int i = threadIdx.x; i < EE * FF; i += blockDim.x) sa[i] = alphas[i];
    __syncthreads();

    const float inv_d = 1.0f / (float)DD;
    for (int pid = blockIdx.x * blockDim.x + threadIdx.x; pid < NPIX_OUT;
         pid += gridDim.x * blockDim.x) {
        int ow  = pid % OW;
        int tmp = pid / OW;
        int oh  = tmp % OH;
        int b   = tmp / OH;
        uint4 win[9];
        float ssum = 0.f;
        #pragma unroll
        for (int dy = 0; dy < 3; dy++)
            #pragma unroll
            for (int dx = 0; dx < 3; dx++) {
                int p = (b * HH + oh + dy) * WW + (ow + dx);
                win[dy * 3 + dx] = reinterpret_cast<const uint4*>(g_xbits)[p];
                ssum += g_S[p];
            }
        float beta = ssum * inv_d;
        size_t obase = (size_t)pid * FF;
        for (int f0 = 0; f0 < FF; f0 += 4) {
            float4 r;
            #pragma unroll
            for (int fi = 0; fi < 4; fi++) {
                int f = f0 + fi;
                const uint4* kb = reinterpret_cast<const uint4*>(skb + f * (EE * 9 * CWRD));
                int p0 = 0, p1 = 0, p2 = 0;
                #pragma unroll
                for (int t = 0; t < 9; t++) {
                    uint4 xv = win[t];
                    uint4 k0 = kb[t], k1 = kb[9 + t], k2 = kb[18 + t];
                    p0 += __popc(xv.x ^ k0.x) + __popc(xv.y ^ k0.y) + __popc(xv.z ^ k0.z) + __popc(xv.w ^ k0.w);
                    p1 += __popc(xv.x ^ k1.x) + __popc(xv.y ^ k1.y) + __popc(xv.z ^ k1.z) + __popc(xv.w ^ k1.w);
                    p2 += __popc(xv.x ^ k2.x) + __popc(xv.y ^ k2.y) + __popc(xv.z ^ k2.z) + __popc(xv.w ^ k2.w);
                }
                float val = sa[f] * (float)(DD - 2 * p0) + sa[FF + f] * (float)(DD - 2 * p1)
                          + sa[2 * FF + f] * (float)(DD - 2 * p2);
                (&r.x)[fi] = beta * val;
            }
            *reinterpret_cast<float4*>(out + obase + f0) = r;
        }
    }
#endif  // !HAS_TCG
}

// ---------------------------------------------------------------------------
extern "C" void kernel_launch(void* const* d_in, const int* in_sizes, int n_in,
                              void* d_out, int out_size) {
    const float* x = (const float*)d_in[0];
    const float* k = (const float*)d_in[1];
    const float* a = (const float*)d_in[2];
    float* out = (float*)d_out;

    binarize_kernel<<<NPIX_IN / 8, 256>>>(x);
    wpack_kernel<<<(9 * CINC * FF) / 256, 256>>>(k, a);
    kpack_kernel<<<KWORDS / 8, 256>>>(k);
    beta_kernel<<<(NPIX_OUT + 255) / 256, 256>>>();

    cudaFuncSetAttribute(abc_mma2_kernel,
                         cudaFuncAttributeMaxDynamicSharedMemorySize, SMEM_TOT);
    cudaFuncSetAttribute(abc_popc_kernel,
                         cudaFuncAttributeMaxDynamicSharedMemorySize, POPC_SMEM);
    // popc (empty on sm_103a) launched before mma2 so the ncu -s window lands on mma2
    abc_popc_kernel<<<296, 256, POPC_SMEM>>>(a, out);
    abc_mma2_kernel<<<BB * 8, 192, SMEM_TOT>>>(out);
}

// round 6
// speedup vs baseline: 6.5222x; 1.1213x over previous
#include <cuda_runtime.h>
#include <cuda_fp16.h>
#include <cstdint>

// ---------------- problem constants ----------------
#define BB 16
#define HH 112
#define WW 112
#define CINC 128
#define FF 256
#define EE 3
#define OH 110
#define OW 110
#define NPIX_IN  (BB * HH * WW)
#define NPIX_OUT (BB * OH * OW)
#define DD 1152
#define CWRD 4

#if defined(__CUDA_ARCH__) && defined(__CUDA_ARCH_FEAT_SM103_ALL)
#define HAS_TCG 1
#else
#define HAS_TCG 0
#endif

// A row buffer: 112 px x 128 ch fp16, blocked SW128 atoms, cc stride 14336B.
#define RB 28672
// B tile (per dy): 96 n-rows (n = dx*32+f) x 128 ch fp16, blocked SW128,
// cc chunk stride 12288B. 24576B per tile, 3 tiles per filter slice.
#define BT 24576
#define NA 5                                // A ring slots

// smem layout (main kernel)
#define SM_TMEM   0
#define SM_BBAR   64
#define SM_FULL(i)  (128 + (i) * 16)
#define SM_EMPTY(i) (224 + (i) * 16)
#define SM_ACC(p)   (320 + (p) * 16)
#define SM_EPI(p)   (384 + (p) * 16)
#define SMEM_A    1024
#define SMEM_B    (SMEM_A + NA * RB)        // 144384 (1024-aligned)
#define ST_D1     (SMEM_B + 3 * BT)         // 218112
#define ST_D2     (ST_D1 + 2 * 128 * 4)     // 219136
#define SMEM_TOT  (ST_D2 + 2 * 256 * 4 + 64)  // 221248

// popc fallback smem
#define KWORDS (FF * EE * 9 * CWRD)
#define POPC_SMEM ((KWORDS + EE * FF) * 4)

// idesc: kind::f16 fp16 inputs, fp32 accum, M=128, N=96
#define MMA_IDESC ((1u << 4) | ((96 / 8) << 17) | ((128 / 16) << 24))

// ---------------- scratch (device globals) ----------------
__device__ __align__(1024) unsigned char g_xq[(size_t)BB * HH * RB + 32768];
__device__ __align__(1024) unsigned char g_w[(size_t)8 * 3 * BT];
__device__ float    g_S[NPIX_IN];
__device__ float    g_beta[NPIX_OUT];
__device__ unsigned g_xbits[NPIX_IN * CWRD];
__device__ unsigned g_kbits[KWORDS];

// ---------------- generic PTX helpers ----------------
__device__ __forceinline__ uint32_t smem_u32(const void* p) {
    uint32_t a;
    asm("{ .reg .u64 t; cvta.to.shared.u64 t, %1; cvt.u32.u64 %0, t; }" : "=r"(a) : "l"(p));
    return a;
}
__device__ __forceinline__ uint32_t elect_one() {
    uint32_t pred;
    asm volatile("{\n\t.reg .pred p;\n\telect.sync _|p, 0xFFFFFFFF;\n\tselp.b32 %0, 1, 0, p;\n\t}" : "=r"(pred));
    return pred;
}
#define MBARRIER_INIT(a, c) \
    asm volatile("mbarrier.init.shared.b64 [%0], %1;" :: "r"((uint32_t)(a)), "r"((uint32_t)(c)) : "memory")
#define MBARRIER_EXPECT_TX(a, b) \
    asm volatile("mbarrier.arrive.expect_tx.shared.b64 _, [%0], %1;" :: "r"((uint32_t)(a)), "r"((uint32_t)(b)) : "memory")
#define MBARRIER_ARRIVE(a) \
    asm volatile("mbarrier.arrive.shared.b64 _, [%0];" :: "r"((uint32_t)(a)) : "memory")
#define MBARRIER_INVAL(a) \
    asm volatile("mbarrier.inval.shared.b64 [%0];" :: "r"((uint32_t)(a)) : "memory")
#define MBARRIER_WAIT(a, par) do {                                           \
    uint32_t _m = (uint32_t)(a); uint32_t _p = (uint32_t)(par);              \
    asm volatile("{\n\t.reg .pred P1;\n\t"                                   \
        "WAIT_LP_%=:\n\t"                                                    \
        "mbarrier.try_wait.parity.acquire.cta.shared::cta.b64 P1, [%0], %1, 0x989680;\n\t" \
        "@P1 bra.uni WAIT_DN_%=;\n\t"                                        \
        "bra.uni WAIT_LP_%=;\n\t"                                            \
        "WAIT_DN_%=:\n\t}" :: "r"(_m), "r"(_p) : "memory");                  \
} while (0)
#define BULK_G2S(dst, src, bytes, mbar) \
    asm volatile("cp.async.bulk.shared::cluster.global.mbarrier::complete_tx::bytes [%0], [%1], %2, [%3];" \
        :: "r"((uint32_t)(dst)), "l"(src), "r"((uint32_t)(bytes)), "r"((uint32_t)(mbar)) : "memory")

// ---------------- tcgen05 helpers (sm_103a only) ----------------
#if HAS_TCG
#define TCGEN05_ALLOC(sa, n) \
    asm volatile("tcgen05.alloc.cta_group::1.sync.aligned.shared::cta.b32 [%0], %1;" \
        :: "r"((uint32_t)(sa)), "r"((uint32_t)(n)) : "memory")
#define TCGEN05_DEALLOC(t, n) \
    asm volatile("tcgen05.dealloc.cta_group::1.sync.aligned.b32 %0, %1;" :: "r"(t), "r"((uint32_t)(n)))
#define TCGEN05_RELINQ() \
    asm volatile("tcgen05.relinquish_alloc_permit.cta_group::1.sync.aligned;")
#define TCGEN05_COMMIT(mb) \
    asm volatile("tcgen05.commit.cta_group::1.mbarrier::arrive::one.shared::cluster.b64 [%0];" \
        :: "r"((uint32_t)(mb)) : "memory")
#define TCGEN05_FENCE_AFTER()  asm volatile("tcgen05.fence::after_thread_sync;" ::: "memory")
#define TCGEN05_FENCE_BEFORE() asm volatile("tcgen05.fence::before_thread_sync;" ::: "memory")
#define TCGEN05_WAIT_LD()      asm volatile("tcgen05.wait::ld.sync.aligned;" ::: "memory")

#define TCGEN05_LD_X32(r, ta)                                                 \
    asm volatile("tcgen05.ld.sync.aligned.32x32b.x32.b32 "                    \
        "{%0, %1, %2, %3, %4, %5, %6, %7, %8, %9, %10, %11, %12, %13, %14, %15, " \
        " %16, %17, %18, %19, %20, %21, %22, %23, %24, %25, %26, %27, %28, %29, %30, %31}, [%32];" \
        : "=r"((r)[0]), "=r"((r)[1]), "=r"((r)[2]), "=r"((r)[3]),             \
          "=r"((r)[4]), "=r"((r)[5]), "=r"((r)[6]), "=r"((r)[7]),             \
          "=r"((r)[8]), "=r"((r)[9]), "=r"((r)[10]), "=r"((r)[11]),           \
          "=r"((r)[12]), "=r"((r)[13]), "=r"((r)[14]), "=r"((r)[15]),         \
          "=r"((r)[16]), "=r"((r)[17]), "=r"((r)[18]), "=r"((r)[19]),         \
          "=r"((r)[20]), "=r"((r)[21]), "=r"((r)[22]), "=r"((r)[23]),         \
          "=r"((r)[24]), "=r"((r)[25]), "=r"((r)[26]), "=r"((r)[27]),         \
          "=r"((r)[28]), "=r"((r)[29]), "=r"((r)[30]), "=r"((r)[31])          \
        : "r"(ta))

__device__ __forceinline__ void mma_f16_ss(uint32_t d, uint64_t adesc, uint64_t bdesc,
                                           uint32_t idesc, uint32_t en) {
    asm volatile(
        "{\n\t.reg .pred p;\n\tsetp.ne.u32 p, %5, 0;\n\t"
        "tcgen05.mma.cta_group::1.kind::f16 [%0], %1, %2, %3, {%4, %4, %4, %4}, p;\n\t}"
        :: "r"(d), "l"(adesc), "l"(bdesc), "r"(idesc), "r"(0u), "r"(en) : "memory");
}

// SW128 K-major descriptor, 1024-aligned bases only.
__device__ __forceinline__ uint64_t make_desc(uint32_t addr) {
    return (uint64_t(2) << 61) | (uint64_t(1) << 46) | (uint64_t(64) << 32) | (uint64_t(1) << 16)
         | ((uint64_t)((addr >> 4) & 0x3FFF));
}
#endif  // HAS_TCG

// ---------------------------------------------------------------------------
// Prep 1: binarize x; one warp per input pixel. Always computes g_S.
// ---------------------------------------------------------------------------
__global__ __launch_bounds__(256) void binarize_kernel(const float* __restrict__ x) {
    int warp = (blockIdx.x * 256 + threadIdx.x) >> 5;
    int lane = threadIdx.x & 31;
    if (warp >= NPIX_IN) return;

    const float4 v = reinterpret_cast<const float4*>(x + (size_t)warp * CINC)[lane];
    float s = fabsf(v.x) + fabsf(v.y) + fabsf(v.z) + fabsf(v.w);
    #pragma unroll
    for (int off = 16; off > 0; off >>= 1) s += __shfl_xor_sync(0xFFFFFFFFu, s, off);
    if (lane == 0) g_S[warp] = s;

#if HAS_TCG
    unsigned h01 = (v.x >= 0.f ? 0x3C00u : 0xBC00u) | ((v.y >= 0.f ? 0x3C00u : 0xBC00u) << 16);
    unsigned h23 = (v.z >= 0.f ? 0x3C00u : 0xBC00u) | ((v.w >= 0.f ? 0x3C00u : 0xBC00u) << 16);
    int w  = warp % WW;
    int ro = warp / WW;
    int c  = lane * 4;
    unsigned o = (unsigned)(c >> 6) * 14336 + (unsigned)w * 128 + (c & 63) * 2;
    unsigned swz = o ^ ((o >> 3) & 0x70);
    *reinterpret_cast<uint2*>(g_xq + (size_t)ro * RB + swz) = make_uint2(h01, h23);
#else
    unsigned nib = (v.x >= 0.f ? 1u : 0u) | (v.y >= 0.f ? 2u : 0u)
                 | (v.z >= 0.f ? 4u : 0u) | (v.w >= 0.f ? 8u : 0u);
    unsigned wv = nib << (4 * (lane & 7));
    wv |= __shfl_xor_sync(0xFFFFFFFFu, wv, 1);
    wv |= __shfl_xor_sync(0xFFFFFFFFu, wv, 2);
    wv |= __shfl_xor_sync(0xFFFFFFFFu, wv, 4);
    if ((lane & 7) == 0) g_xbits[warp * CWRD + (lane >> 3)] = wv;
#endif
}

// ---------------------------------------------------------------------------
// Prep 2a (sm_103a): Wc[tap,c,f] = sum_e alpha[e,f]*sign(K[e,tap,c,f]), fp16.
// Layout: per filter-slice fs, 3 tiles (dy); tile rows n = dx*32 + (f&31),
// 128 ch per row, blocked SW128 (cc chunk stride 12288B).
// ---------------------------------------------------------------------------
__global__ __launch_bounds__(256) void wpack_kernel(const float* __restrict__ k,
                                                    const float* __restrict__ alphas) {
#if HAS_TCG
    int tid = blockIdx.x * 256 + threadIdx.x;
    if (tid >= 9 * CINC * FF) return;
    int f = tid & 255;
    int c = (tid >> 8) & 127;
    int tap = tid >> 15;              // 0..8, = dy*3+dx
    int dy = tap / 3, dx = tap % 3;

    float wc = 0.f;
    #pragma unroll
    for (int e = 0; e < EE; e++) {
        float kv = k[(((size_t)e * 9 + tap) * CINC + c) * FF + f];
        float a  = alphas[e * FF + f];
        wc += (kv >= 0.f) ? a : -a;
    }
    int fs = f >> 5;
    int n  = dx * 32 + (f & 31);      // row within N=96 tile
    unsigned o = (unsigned)(c >> 6) * 12288 + (unsigned)n * 128 + (c & 63) * 2;
    unsigned swz = o ^ ((o >> 3) & 0x70);
    *reinterpret_cast<unsigned short*>(g_w + (size_t)(fs * 3 + dy) * BT + swz) =
        __half_as_ushort(__float2half_rn(wc));
#endif
}

// Prep 2b (fallback): packed kernel sign bits.
__global__ __launch_bounds__(256) void kpack_kernel(const float* __restrict__ k) {
#if !HAS_TCG
    int idx  = (blockIdx.x * blockDim.x + threadIdx.x) >> 5;
    int lane = threadIdx.x & 31;
    if (idx >= KWORDS) return;
    int w   = idx & (CWRD - 1);
    int t3  = idx >> 2;
    int tap = t3 % 9;
    int fe  = t3 / 9;
    int e   = fe % EE;
    int f   = fe / EE;
    int c   = w * 32 + lane;
    float val = k[((size_t)(e * 9 + tap) * CINC + c) * FF + f];
    unsigned bits = __ballot_sync(0xFFFFFFFFu, val >= 0.f);
    if (lane == 0) g_kbits[idx] = bits;
#endif
}

// Prep 3 (sm_103a): beta image.
__global__ __launch_bounds__(256) void beta_kernel() {
#if HAS_TCG
    int pid = blockIdx.x * 256 + threadIdx.x;
    if (pid >= NPIX_OUT) return;
    int ow = pid % OW;
    int t  = pid / OW;
    int oh = t % OH;
    int b  = t / OH;
    float s = 0.f;
    #pragma unroll
    for (int dy = 0; dy < 3; dy++)
        #pragma unroll
        for (int dx = 0; dx < 3; dx++)
            s += g_S[(b * HH + oh + dy) * WW + (ow + dx)];
    g_beta[pid] = s * (1.0f / (float)DD);
#endif
}

// ---------------------------------------------------------------------------
// Main (sm_103a): persistent implicit-GEMM conv, CTA = (batch, 32-filter slice).
// Per output row ONE N=96 accumulator (cols = dx*32+f), 24 dispatches
// (3 dy x 2 cc x 4 k), 1 commit. dx applied by lane shift in the epilogue.
// B resident (3 x 24KB); A rows in 5-slot ring. TMEM pipeline p = oh&3.
// Warps 0-3 epilogue, 4 producer, 5 MMA.
// ---------------------------------------------------------------------------
__global__ __launch_bounds__(192, 1) void abc_mma2_kernel(float* __restrict__ out) {
#if HAS_TCG
    extern __shared__ char smem[];
    const uint32_t sb = smem_u32(smem);
    const int tid = threadIdx.x;
    const int wid = tid >> 5;
    const int lane = tid & 31;
    const int b  = blockIdx.x >> 3;
    const int fs = blockIdx.x & 7;

    if (tid == 0) {
        MBARRIER_INIT(sb + SM_BBAR, 1);
        #pragma unroll
        for (int i = 0; i < NA; i++) {
            MBARRIER_INIT(sb + SM_FULL(i), 1);
            MBARRIER_INIT(sb + SM_EMPTY(i), 1);
        }
        #pragma unroll
        for (int i = 0; i < 4; i++) {
            MBARRIER_INIT(sb + SM_ACC(i), 1);
            MBARRIER_INIT(sb + SM_EPI(i), 4);
        }
    }
    if (wid == 5) { TCGEN05_ALLOC(sb + SM_TMEM, 512); TCGEN05_RELINQ(); }
    __syncthreads();
    uint32_t tbase;
    asm volatile("ld.shared.b32 %0, [%1];" : "=r"(tbase) : "r"(sb + SM_TMEM));

    // ---------------- producer (warp 4) ----------------
    if (wid == 4) {
        if (elect_one()) {
            MBARRIER_EXPECT_TX(sb + SM_BBAR, 3 * BT);
            #pragma unroll
            for (int t = 0; t < 3; t++)
                BULK_G2S(sb + SMEM_B + t * BT, g_w + (size_t)(fs * 3 + t) * BT, BT, sb + SM_BBAR);
            int eph[NA] = {0, 0, 0, 0, 0};
            int s = 0;
            for (int r = 0; r < HH; r++) {
                if (r >= NA) { MBARRIER_WAIT(sb + SM_EMPTY(s), eph[s]); eph[s] ^= 1; }
                MBARRIER_EXPECT_TX(sb + SM_FULL(s), RB);
                BULK_G2S(sb + SMEM_A + s * RB, g_xq + (size_t)(b * HH + r) * RB, RB, sb + SM_FULL(s));
                if (++s == NA) s = 0;
            }
        }
    }

    // ---------------- MMA (warp 5) ----------------
    if (wid == 5) {
        // K-step descriptor offsets (16B units): A cc1 at +14336B, B cc1 at +12288B
        const uint32_t akoff[8] = {0, 2, 4, 6, 896, 898, 900, 902};
        const uint32_t bkoff[8] = {0, 2, 4, 6, 768, 770, 772, 774};
        MBARRIER_WAIT(sb + SM_BBAR, 0);
        int fph[NA] = {0, 0, 0, 0, 0};
        MBARRIER_WAIT(sb + SM_FULL(0), 0); fph[0] = 1;
        MBARRIER_WAIT(sb + SM_FULL(1), 0); fph[1] = 1;
        int snew = 2;                       // slot of row oh+2
        int srel = 0;                       // slot of row oh (released after use)
        for (int oh = 0; oh < OH; oh++) {
            MBARRIER_WAIT(sb + SM_FULL(snew), fph[snew]); fph[snew] ^= 1;
            if (oh >= 4) MBARRIER_WAIT(sb + SM_EPI(oh & 3), ((oh >> 2) - 1) & 1);
            TCGEN05_FENCE_AFTER();
            if (elect_one()) {
                uint32_t dacc = tbase + (oh & 3) * 96;
                int s0 = srel;
                #pragma unroll
                for (int dy = 0; dy < 3; dy++) {
                    int sl = s0 + dy; if (sl >= NA) sl -= NA;
                    uint64_t ad = make_desc(sb + SMEM_A + sl * RB);
                    uint64_t bd = make_desc(sb + SMEM_B + dy * BT);
                    #pragma unroll
                    for (int k = 0; k < 8; k++)
                        mma_f16_ss(dacc, ad + akoff[k], bd + bkoff[k], MMA_IDESC,
                                   !(dy == 0 && k == 0));
                }
                TCGEN05_COMMIT(sb + SM_EMPTY(srel));
                TCGEN05_COMMIT(sb + SM_ACC(oh & 3));
            }
            if (++snew == NA) snew = 0;
            if (++srel == NA) srel = 0;
        }
    }

    // ---------------- epilogue (warps 0-3) ----------------
    if (wid < 4) {
        float* sD1 = reinterpret_cast<float*>(smem + ST_D1);
        float* sD2 = reinterpret_cast<float*>(smem + ST_D2);
        for (int oh = 0; oh < OH; oh++) {
            int p  = oh & 3;
            int p2 = oh & 1;
            MBARRIER_WAIT(sb + SM_ACC(p), (oh >> 2) & 1);
            TCGEN05_FENCE_AFTER();
            uint32_t r0[32], r1[32], r2[32];
            TCGEN05_LD_X32(r0, tbase + p * 96);
            TCGEN05_LD_X32(r1, tbase + p * 96 + 32);
            TCGEN05_LD_X32(r2, tbase + p * 96 + 64);
            TCGEN05_WAIT_LD();
            TCGEN05_FENCE_BEFORE();
            if (elect_one()) MBARRIER_ARRIVE(sb + SM_EPI(p));  // free accumulator early

            if (wid > 0 && lane < 2) {
                #pragma unroll
                for (int j = 0; j < 32; j++) {
                    if (lane == 0) sD1[p2 * 128 + wid * 32 + j] = __uint_as_float(r1[j]);
                    sD2[p2 * 256 + (wid * 2 + lane) * 32 + j] = __uint_as_float(r2[j]);
                }
            }
            asm volatile("bar.sync 1, 128;" ::: "memory");

            int ow = wid * 32 + lane;
            bool valid = (ow < OW);
            float beta = 0.f;
            int pid = 0;
            if (valid) {
                pid = (b * OH + oh) * OW + ow;
                beta = g_beta[pid];
            }
            float v[32];
            #pragma unroll
            for (int j = 0; j < 32; j++) {
                float f0 = __uint_as_float(r0[j]);
                float f1 = __uint_as_float(__shfl_down_sync(0xFFFFFFFFu, r1[j], 1));
                float f2 = __uint_as_float(__shfl_down_sync(0xFFFFFFFFu, r2[j], 2));
                if (lane == 31 && wid < 3) f1 = sD1[p2 * 128 + (wid + 1) * 32 + j];
                if (lane >= 30 && wid < 3) f2 = sD2[p2 * 256 + ((wid + 1) * 2 + (lane - 30)) * 32 + j];
                v[j] = beta * (f0 + f1 + f2);
            }
            if (valid) {
                float* ob = out + (size_t)pid * FF + fs * 32;
                #pragma unroll
                for (int q = 0; q < 8; q++)
                    *reinterpret_cast<float4*>(ob + q * 4) =
                        make_float4(v[q * 4], v[q * 4 + 1], v[q * 4 + 2], v[q * 4 + 3]);
            }
        }
    }

    __syncthreads();
    if (tid == 0) {
        MBARRIER_INVAL(sb + SM_BBAR);
        #pragma unroll
        for (int i = 0; i < NA; i++) { MBARRIER_INVAL(sb + SM_FULL(i)); MBARRIER_INVAL(sb + SM_EMPTY(i)); }
        #pragma unroll
        for (int i = 0; i < 4; i++) { MBARRIER_INVAL(sb + SM_ACC(i)); MBARRIER_INVAL(sb + SM_EPI(i)); }
    }
    if (wid == 5) TCGEN05_DEALLOC(tbase, 512);
#endif  // HAS_TCG
}

// ---------------------------------------------------------------------------
// Fallback main (non-103a passes): R1 popcount kernel.
// ---------------------------------------------------------------------------
__global__ __launch_bounds__(256) void abc_popc_kernel(
    const float* __restrict__ alphas, float* __restrict__ out) {
#if !HAS_TCG
    extern __shared__ unsigned skb[];
    float* sa = reinterpret_cast<float*>(skb + KWORDS);
    for (int i = threadIdx.x; i < KWORDS; i += blockDim.x) skb[i] = g_kbits[i];
    for (int i = threadIdx.x; i < EE * FF; i += blockDim.x) sa[i] = alphas[i];
    __syncthreads();

    const float inv_d = 1.0f / (float)DD;
    for (int pid = blockIdx.x * blockDim.x + threadIdx.x; pid < NPIX_OUT;
         pid += gridDim.x * blockDim.x) {
        int ow  = pid % OW;
        int tmp = pid / OW;
        int oh  = tmp % OH;
        int b   = tmp / OH;
        uint4 win[9];
        float ssum = 0.f;
        #pragma unroll
        for (int dy = 0; dy < 3; dy++)
            #pragma unroll
            for (int dx = 0; dx < 3; dx++) {
                int p = (b * HH + oh + dy) * WW + (ow + dx);
                win[dy * 3 + dx] = reinterpret_cast<const uint4*>(g_xbits)[p];
                ssum += g_S[p];
            }
        float beta = ssum * inv_d;
        size_t obase = (size_t)pid * FF;
        for (int f0 = 0; f0 < FF; f0 += 4) {
            float4 r;
            #pragma unroll
            for (int fi = 0; fi < 4; fi++) {
                int f = f0 + fi;
                const uint4* kb = reinterpret_cast<const uint4*>(skb + f * (EE * 9 * CWRD));
                int p0 = 0, p1 = 0, p2 = 0;
                #pragma unroll
                for (int t = 0; t < 9; t++) {
                    uint4 xv = win[t];
                    uint4 k0 = kb[t], k1 = kb[9 + t], k2 = kb[18 + t];
                    p0 += __popc(xv.x ^ k0.x) + __popc(xv.y ^ k0.y) + __popc(xv.z ^ k0.z) + __popc(xv.w ^ k0.w);
                    p1 += __popc(xv.x ^ k1.x) + __popc(xv.y ^ k1.y) + __popc(xv.z ^ k1.z) + __popc(xv.w ^ k1.w);
                    p2 += __popc(xv.x ^ k2.x) + __popc(xv.y ^ k2.y) + __popc(xv.z ^ k2.z) + __popc(xv.w ^ k2.w);
                }
                float val = sa[f] * (float)(DD - 2 * p0) + sa[FF + f] * (float)(DD - 2 * p1)
                          + sa[2 * FF + f] * (float)(DD - 2 * p2);
                (&r.x)[fi] = beta * val;
            }
            *reinterpret_cast<float4*>(out + obase + f0) = r;
        }
    }
#endif  // !HAS_TCG
}

// ---------------------------------------------------------------------------
extern "C" void kernel_launch(void* const* d_in, const int* in_sizes, int n_in,
                              void* d_out, int out_size) {
    const float* x = (const float*)d_in[0];
    const float* k = (const float*)d_in[1];
    const float* a = (const float*)d_in[2];
    float* out = (float*)d_out;

    binarize_kernel<<<NPIX_IN / 8, 256>>>(x);
    wpack_kernel<<<(9 * CINC * FF) / 256, 256>>>(k, a);
    kpack_kernel<<<KWORDS / 8, 256>>>(k);
    beta_kernel<<<(NPIX_OUT + 255) / 256, 256>>>();

    cudaFuncSetAttribute(abc_mma2_kernel,
                         cudaFuncAttributeMaxDynamicSharedMemorySize, SMEM_TOT);
    cudaFuncSetAttribute(abc_popc_kernel,
                         cudaFuncAttributeMaxDynamicSharedMemorySize, POPC_SMEM);
    abc_popc_kernel<<<296, 256, POPC_SMEM>>>(a, out);
    abc_mma2_kernel<<<BB * 8, 192, SMEM_TOT>>>(out);
}

// round 9
// speedup vs baseline: 7.0907x; 1.0872x over previous
#include <cuda_runtime.h>
#include <cuda_fp16.h>
#include <cstdint>

// ---------------- problem constants ----------------
#define BB 16
#define HH 112
#define WW 112
#define CINC 128
#define FF 256
#define EE 3
#define OH 110
#define OW 110
#define NPIX_IN  (BB * HH * WW)
#define NPIX_OUT (BB * OH * OW)
#define DD 1152
#define CWRD 4

#if defined(__CUDA_ARCH__) && defined(__CUDA_ARCH_FEAT_SM103_ALL)
#define HAS_TCG 1
#else
#define HAS_TCG 0
#endif

// A row buffer: 112 px x 128 ch fp16, blocked SW128 atoms, cc stride 14336B.
#define RB 28672
// B tile (per dy): 96 n-rows (n = dx*32+f) x 128 ch fp16, blocked SW128,
// cc chunk stride 12288B. 24576B per tile, 3 tiles per filter slice.
#define BT 24576
#define NA 5                                // A ring slots
#define NTHREADS 320                        // 8 epi + 1 producer + 1 mma warps

// smem layout (main kernel)
#define SM_TMEM   0
#define SM_BBAR   64
#define SM_FULL(i)  (128 + (i) * 16)
#define SM_EMPTY(i) (224 + (i) * 16)
#define SM_ACC(p)   (320 + (p) * 16)
#define SM_EPI(p)   (384 + (p) * 16)
#define SMEM_A    1024
#define SMEM_B    (SMEM_A + NA * RB)        // 144384 (1024-aligned)
#define ST_D1     (SMEM_B + 3 * BT)         // 218112; 4 x 128 floats
#define ST_D2     (ST_D1 + 4 * 128 * 4)     // 220160; 4 x 256 floats
#define SMEM_TOT  (ST_D2 + 4 * 256 * 4 + 64)  // 224320

// popc fallback smem
#define KWORDS (FF * EE * 9 * CWRD)
#define POPC_SMEM ((KWORDS + EE * FF) * 4)

// idesc: kind::f16 fp16 inputs, fp32 accum, M=128, N=96
#define MMA_IDESC ((1u << 4) | ((96 / 8) << 17) | ((128 / 16) << 24))

// ---------------- scratch (device globals) ----------------
__device__ __align__(1024) unsigned char g_xq[(size_t)BB * HH * RB + 32768];
__device__ __align__(1024) unsigned char g_w[(size_t)8 * 3 * BT];
__device__ float    g_S[NPIX_IN];
__device__ float    g_beta[NPIX_OUT];
__device__ unsigned g_xbits[NPIX_IN * CWRD];
__device__ unsigned g_kbits[KWORDS];

// ---------------- generic PTX helpers ----------------
__device__ __forceinline__ uint32_t smem_u32(const void* p) {
    uint32_t a;
    asm("{ .reg .u64 t; cvta.to.shared.u64 t, %1; cvt.u32.u64 %0, t; }" : "=r"(a) : "l"(p));
    return a;
}
__device__ __forceinline__ uint32_t elect_one() {
    uint32_t pred;
    asm volatile("{\n\t.reg .pred p;\n\telect.sync _|p, 0xFFFFFFFF;\n\tselp.b32 %0, 1, 0, p;\n\t}" : "=r"(pred));
    return pred;
}
#define MBARRIER_INIT(a, c) \
    asm volatile("mbarrier.init.shared.b64 [%0], %1;" :: "r"((uint32_t)(a)), "r"((uint32_t)(c)) : "memory")
#define MBARRIER_EXPECT_TX(a, b) \
    asm volatile("mbarrier.arrive.expect_tx.shared.b64 _, [%0], %1;" :: "r"((uint32_t)(a)), "r"((uint32_t)(b)) : "memory")
#define MBARRIER_ARRIVE(a) \
    asm volatile("mbarrier.arrive.shared.b64 _, [%0];" :: "r"((uint32_t)(a)) : "memory")
#define MBARRIER_INVAL(a) \
    asm volatile("mbarrier.inval.shared.b64 [%0];" :: "r"((uint32_t)(a)) : "memory")
#define MBARRIER_WAIT(a, par) do {                                           \
    uint32_t _m = (uint32_t)(a); uint32_t _p = (uint32_t)(par);              \
    asm volatile("{\n\t.reg .pred P1;\n\t"                                   \
        "WAIT_LP_%=:\n\t"                                                    \
        "mbarrier.try_wait.parity.acquire.cta.shared::cta.b64 P1, [%0], %1, 0x989680;\n\t" \
        "@P1 bra.uni WAIT_DN_%=;\n\t"                                        \
        "bra.uni WAIT_LP_%=;\n\t"                                            \
        "WAIT_DN_%=:\n\t}" :: "r"(_m), "r"(_p) : "memory");                  \
} while (0)
#define BULK_G2S(dst, src, bytes, mbar) \
    asm volatile("cp.async.bulk.shared::cluster.global.mbarrier::complete_tx::bytes [%0], [%1], %2, [%3];" \
        :: "r"((uint32_t)(dst)), "l"(src), "r"((uint32_t)(bytes)), "r"((uint32_t)(mbar)) : "memory")

// ---------------- tcgen05 helpers (sm_103a only) ----------------
#if HAS_TCG
#define TCGEN05_ALLOC(sa, n) \
    asm volatile("tcgen05.alloc.cta_group::1.sync.aligned.shared::cta.b32 [%0], %1;" \
        :: "r"((uint32_t)(sa)), "r"((uint32_t)(n)) : "memory")
#define TCGEN05_DEALLOC(t, n) \
    asm volatile("tcgen05.dealloc.cta_group::1.sync.aligned.b32 %0, %1;" :: "r"(t), "r"((uint32_t)(n)))
#define TCGEN05_RELINQ() \
    asm volatile("tcgen05.relinquish_alloc_permit.cta_group::1.sync.aligned;")
#define TCGEN05_COMMIT(mb) \
    asm volatile("tcgen05.commit.cta_group::1.mbarrier::arrive::one.shared::cluster.b64 [%0];" \
        :: "r"((uint32_t)(mb)) : "memory")
#define TCGEN05_FENCE_AFTER()  asm volatile("tcgen05.fence::after_thread_sync;" ::: "memory")
#define TCGEN05_FENCE_BEFORE() asm volatile("tcgen05.fence::before_thread_sync;" ::: "memory")
#define TCGEN05_WAIT_LD()      asm volatile("tcgen05.wait::ld.sync.aligned;" ::: "memory")

#define TCGEN05_LD_X32(r, ta)                                                 \
    asm volatile("tcgen05.ld.sync.aligned.32x32b.x32.b32 "                    \
        "{%0, %1, %2, %3, %4, %5, %6, %7, %8, %9, %10, %11, %12, %13, %14, %15, " \
        " %16, %17, %18, %19, %20, %21, %22, %23, %24, %25, %26, %27, %28, %29, %30, %31}, [%32];" \
        : "=r"((r)[0]), "=r"((r)[1]), "=r"((r)[2]), "=r"((r)[3]),             \
          "=r"((r)[4]), "=r"((r)[5]), "=r"((r)[6]), "=r"((r)[7]),             \
          "=r"((r)[8]), "=r"((r)[9]), "=r"((r)[10]), "=r"((r)[11]),           \
          "=r"((r)[12]), "=r"((r)[13]), "=r"((r)[14]), "=r"((r)[15]),         \
          "=r"((r)[16]), "=r"((r)[17]), "=r"((r)[18]), "=r"((r)[19]),         \
          "=r"((r)[20]), "=r"((r)[21]), "=r"((r)[22]), "=r"((r)[23]),         \
          "=r"((r)[24]), "=r"((r)[25]), "=r"((r)[26]), "=r"((r)[27]),         \
          "=r"((r)[28]), "=r"((r)[29]), "=r"((r)[30]), "=r"((r)[31])          \
        : "r"(ta))

__device__ __forceinline__ void mma_f16_ss(uint32_t d, uint64_t adesc, uint64_t bdesc,
                                           uint32_t idesc, uint32_t en) {
    asm volatile(
        "{\n\t.reg .pred p;\n\tsetp.ne.u32 p, %5, 0;\n\t"
        "tcgen05.mma.cta_group::1.kind::f16 [%0], %1, %2, %3, {%4, %4, %4, %4}, p;\n\t}"
        :: "r"(d), "l"(adesc), "l"(bdesc), "r"(idesc), "r"(0u), "r"(en) : "memory");
}

// SW128 K-major descriptor, 1024-aligned bases only.
__device__ __forceinline__ uint64_t make_desc(uint32_t addr) {
    return (uint64_t(2) << 61) | (uint64_t(1) << 46) | (uint64_t(64) << 32) | (uint64_t(1) << 16)
         | ((uint64_t)((addr >> 4) & 0x3FFF));
}
#endif  // HAS_TCG

// ---------------------------------------------------------------------------
// Prep 1: binarize x; one warp per input pixel. Always computes g_S.
// ---------------------------------------------------------------------------
__global__ __launch_bounds__(256) void binarize_kernel(const float* __restrict__ x) {
    int warp = (blockIdx.x * 256 + threadIdx.x) >> 5;
    int lane = threadIdx.x & 31;
    if (warp >= NPIX_IN) return;

    const float4 v = reinterpret_cast<const float4*>(x + (size_t)warp * CINC)[lane];
    float s = fabsf(v.x) + fabsf(v.y) + fabsf(v.z) + fabsf(v.w);
    #pragma unroll
    for (int off = 16; off > 0; off >>= 1) s += __shfl_xor_sync(0xFFFFFFFFu, s, off);
    if (lane == 0) g_S[warp] = s;

#if HAS_TCG
    unsigned h01 = (v.x >= 0.f ? 0x3C00u : 0xBC00u) | ((v.y >= 0.f ? 0x3C00u : 0xBC00u) << 16);
    unsigned h23 = (v.z >= 0.f ? 0x3C00u : 0xBC00u) | ((v.w >= 0.f ? 0x3C00u : 0xBC00u) << 16);
    int w  = warp % WW;
    int ro = warp / WW;
    int c  = lane * 4;
    unsigned o = (unsigned)(c >> 6) * 14336 + (unsigned)w * 128 + (c & 63) * 2;
    unsigned swz = o ^ ((o >> 3) & 0x70);
    *reinterpret_cast<uint2*>(g_xq + (size_t)ro * RB + swz) = make_uint2(h01, h23);
#else
    unsigned nib = (v.x >= 0.f ? 1u : 0u) | (v.y >= 0.f ? 2u : 0u)
                 | (v.z >= 0.f ? 4u : 0u) | (v.w >= 0.f ? 8u : 0u);
    unsigned wv = nib << (4 * (lane & 7));
    wv |= __shfl_xor_sync(0xFFFFFFFFu, wv, 1);
    wv |= __shfl_xor_sync(0xFFFFFFFFu, wv, 2);
    wv |= __shfl_xor_sync(0xFFFFFFFFu, wv, 4);
    if ((lane & 7) == 0) g_xbits[warp * CWRD + (lane >> 3)] = wv;
#endif
}

// ---------------------------------------------------------------------------
// Prep 2a (sm_103a): Wc[tap,c,f] = sum_e alpha[e,f]*sign(K[e,tap,c,f]), fp16.
// Per filter-slice fs: 3 tiles (dy); tile rows n = dx*32 + (f&31), 128 ch,
// blocked SW128 (cc chunk stride 12288B).
// ---------------------------------------------------------------------------
__global__ __launch_bounds__(256) void wpack_kernel(const float* __restrict__ k,
                                                    const float* __restrict__ alphas) {
#if HAS_TCG
    int tid = blockIdx.x * 256 + threadIdx.x;
    if (tid >= 9 * CINC * FF) return;
    int f = tid & 255;
    int c = (tid >> 8) & 127;
    int tap = tid >> 15;              // 0..8, = dy*3+dx
    int dy = tap / 3, dx = tap % 3;

    float wc = 0.f;
    #pragma unroll
    for (int e = 0; e < EE; e++) {
        float kv = k[(((size_t)e * 9 + tap) * CINC + c) * FF + f];
        float a  = alphas[e * FF + f];
        wc += (kv >= 0.f) ? a : -a;
    }
    int fs = f >> 5;
    int n  = dx * 32 + (f & 31);      // row within N=96 tile
    unsigned o = (unsigned)(c >> 6) * 12288 + (unsigned)n * 128 + (c & 63) * 2;
    unsigned swz = o ^ ((o >> 3) & 0x70);
    *reinterpret_cast<unsigned short*>(g_w + (size_t)(fs * 3 + dy) * BT + swz) =
        __half_as_ushort(__float2half_rn(wc));
#endif
}

// Prep 2b (fallback): packed kernel sign bits.
__global__ __launch_bounds__(256) void kpack_kernel(const float* __restrict__ k) {
#if !HAS_TCG
    int idx  = (blockIdx.x * blockDim.x + threadIdx.x) >> 5;
    int lane = threadIdx.x & 31;
    if (idx >= KWORDS) return;
    int w   = idx & (CWRD - 1);
    int t3  = idx >> 2;
    int tap = t3 % 9;
    int fe  = t3 / 9;
    int e   = fe % EE;
    int f   = fe / EE;
    int c   = w * 32 + lane;
    float val = k[((size_t)(e * 9 + tap) * CINC + c) * FF + f];
    unsigned bits = __ballot_sync(0xFFFFFFFFu, val >= 0.f);
    if (lane == 0) g_kbits[idx] = bits;
#endif
}

// Prep 3 (sm_103a): beta image.
__global__ __launch_bounds__(256) void beta_kernel() {
#if HAS_TCG
    int pid = blockIdx.x * 256 + threadIdx.x;
    if (pid >= NPIX_OUT) return;
    int ow = pid % OW;
    int t  = pid / OW;
    int oh = t % OH;
    int b  = t / OH;
    float s = 0.f;
    #pragma unroll
    for (int dy = 0; dy < 3; dy++)
        #pragma unroll
        for (int dx = 0; dx < 3; dx++)
            s += g_S[(b * HH + oh + dy) * WW + (ow + dx)];
    g_beta[pid] = s * (1.0f / (float)DD);
#endif
}

// ---------------------------------------------------------------------------
// Main (sm_103a): persistent implicit-GEMM conv, CTA = (batch, 32-filter slice).
// Per output row ONE N=96 accumulator (cols = dx*32+f), 24 dispatches, 1 commit.
// dx applied by lane shift in the epilogue. B resident; A rows in 5-slot ring.
// TMEM pipeline p = oh&3. TWO epilogue warp-groups: warps 0-3 even rows,
// warps 4-7 odd rows (epilogue fully overlapped with MMA). Warp 8 producer,
// warp 9 MMA.
// ---------------------------------------------------------------------------
__global__ __launch_bounds__(NTHREADS, 1) void abc_mma2_kernel(float* __restrict__ out) {
#if HAS_TCG
    extern __shared__ char smem[];
    const uint32_t sb = smem_u32(smem);
    const int tid = threadIdx.x;
    const int wid = tid >> 5;
    const int lane = tid & 31;
    const int b  = blockIdx.x >> 3;
    const int fs = blockIdx.x & 7;

    if (tid == 0) {
        MBARRIER_INIT(sb + SM_BBAR, 1);
        #pragma unroll
        for (int i = 0; i < NA; i++) {
            MBARRIER_INIT(sb + SM_FULL(i), 1);
            MBARRIER_INIT(sb + SM_EMPTY(i), 1);
        }
        #pragma unroll
        for (int i = 0; i < 4; i++) {
            MBARRIER_INIT(sb + SM_ACC(i), 1);
            MBARRIER_INIT(sb + SM_EPI(i), 4);
        }
    }
    if (wid == 9) { TCGEN05_ALLOC(sb + SM_TMEM, 512); TCGEN05_RELINQ(); }
    __syncthreads();
    uint32_t tbase;
    asm volatile("ld.shared.b32 %0, [%1];" : "=r"(tbase) : "r"(sb + SM_TMEM));

    // ---------------- producer (warp 8) ----------------
    if (wid == 8) {
        if (elect_one()) {
            MBARRIER_EXPECT_TX(sb + SM_BBAR, 3 * BT);
            #pragma unroll
            for (int t = 0; t < 3; t++)
                BULK_G2S(sb + SMEM_B + t * BT, g_w + (size_t)(fs * 3 + t) * BT, BT, sb + SM_BBAR);
            int eph[NA] = {0, 0, 0, 0, 0};
            int s = 0;
            for (int r = 0; r < HH; r++) {
                if (r >= NA) { MBARRIER_WAIT(sb + SM_EMPTY(s), eph[s]); eph[s] ^= 1; }
                MBARRIER_EXPECT_TX(sb + SM_FULL(s), RB);
                BULK_G2S(sb + SMEM_A + s * RB, g_xq + (size_t)(b * HH + r) * RB, RB, sb + SM_FULL(s));
                if (++s == NA) s = 0;
            }
        }
    }

    // ---------------- MMA (warp 9) ----------------
    if (wid == 9) {
        // K-step descriptor offsets (16B units): A cc1 at +14336B, B cc1 at +12288B
        const uint32_t akoff[8] = {0, 2, 4, 6, 896, 898, 900, 902};
        const uint32_t bkoff[8] = {0, 2, 4, 6, 768, 770, 772, 774};
        MBARRIER_WAIT(sb + SM_BBAR, 0);
        int fph[NA] = {0, 0, 0, 0, 0};
        MBARRIER_WAIT(sb + SM_FULL(0), 0); fph[0] = 1;
        MBARRIER_WAIT(sb + SM_FULL(1), 0); fph[1] = 1;
        int snew = 2;                       // slot of row oh+2
        int srel = 0;                       // slot of row oh
        for (int oh = 0; oh < OH; oh++) {
            MBARRIER_WAIT(sb + SM_FULL(snew), fph[snew]); fph[snew] ^= 1;
            if (oh >= 4) MBARRIER_WAIT(sb + SM_EPI(oh & 3), ((oh >> 2) - 1) & 1);
            TCGEN05_FENCE_AFTER();
            if (elect_one()) {
                uint32_t dacc = tbase + (oh & 3) * 96;
                #pragma unroll
                for (int dy = 0; dy < 3; dy++) {
                    int sl = srel + dy; if (sl >= NA) sl -= NA;
                    uint64_t ad = make_desc(sb + SMEM_A + sl * RB);
                    uint64_t bd = make_desc(sb + SMEM_B + dy * BT);
                    #pragma unroll
                    for (int k = 0; k < 8; k++)
                        mma_f16_ss(dacc, ad + akoff[k], bd + bkoff[k], MMA_IDESC,
                                   !(dy == 0 && k == 0));
                }
                TCGEN05_COMMIT(sb + SM_EMPTY(srel));
                TCGEN05_COMMIT(sb + SM_ACC(oh & 3));
            }
            if (++snew == NA) snew = 0;
            if (++srel == NA) srel = 0;
        }
    }

    // ---------------- epilogue (warps 0-7, two groups by row parity) --------
    if (wid < 8) {
        const int g  = wid >> 2;           // group: 0 = even rows, 1 = odd rows
        const int lw = wid & 3;            // warp within group
        float* sD1 = reinterpret_cast<float*>(smem + ST_D1);
        float* sD2 = reinterpret_cast<float*>(smem + ST_D2);
        for (int oh = g; oh < OH; oh += 2) {
            int p = oh & 3;
            int q = g * 2 + ((oh >> 1) & 1);   // staging buffer index (4 sets)
            MBARRIER_WAIT(sb + SM_ACC(p), (oh >> 2) & 1);
            TCGEN05_FENCE_AFTER();
            uint32_t r0[32], r1[32], r2[32];
            TCGEN05_LD_X32(r0, tbase + p * 96);
            TCGEN05_LD_X32(r1, tbase + p * 96 + 32);
            TCGEN05_LD_X32(r2, tbase + p * 96 + 64);
            TCGEN05_WAIT_LD();
            TCGEN05_FENCE_BEFORE();
            if (elect_one()) MBARRIER_ARRIVE(sb + SM_EPI(p));  // free accumulator early

            if (lw > 0 && lane < 2) {
                #pragma unroll
                for (int j = 0; j < 32; j++) {
                    if (lane == 0) sD1[q * 128 + lw * 32 + j] = __uint_as_float(r1[j]);
                    sD2[q * 256 + (lw * 2 + lane) * 32 + j] = __uint_as_float(r2[j]);
                }
            }
            asm volatile("bar.sync %0, 128;" :: "r"(1 + g) : "memory");

            int ow = lw * 32 + lane;
            bool valid = (ow < OW);
            float beta = 0.f;
            int pid = 0;
            if (valid) {
                pid = (b * OH + oh) * OW + ow;
                beta = g_beta[pid];
            }
            float v[32];
            #pragma unroll
            for (int j = 0; j < 32; j++) {
                float f0 = __uint_as_float(r0[j]);
                float f1 = __uint_as_float(__shfl_down_sync(0xFFFFFFFFu, r1[j], 1));
                float f2 = __uint_as_float(__shfl_down_sync(0xFFFFFFFFu, r2[j], 2));
                if (lane == 31 && lw < 3) f1 = sD1[q * 128 + (lw + 1) * 32 + j];
                if (lane >= 30 && lw < 3) f2 = sD2[q * 256 + ((lw + 1) * 2 + (lane - 30)) * 32 + j];
                v[j] = beta * (f0 + f1 + f2);
            }
            if (valid) {
                float* ob = out + (size_t)pid * FF + fs * 32;
                #pragma unroll
                for (int qq = 0; qq < 8; qq++)
                    *reinterpret_cast<float4*>(ob + qq * 4) =
                        make_float4(v[qq * 4], v[qq * 4 + 1], v[qq * 4 + 2], v[qq * 4 + 3]);
            }
        }
    }

    __syncthreads();
    if (tid == 0) {
        MBARRIER_INVAL(sb + SM_BBAR);
        #pragma unroll
        for (int i = 0; i < NA; i++) { MBARRIER_INVAL(sb + SM_FULL(i)); MBARRIER_INVAL(sb + SM_EMPTY(i)); }
        #pragma unroll
        for (int i = 0; i < 4; i++) { MBARRIER_INVAL(sb + SM_ACC(i)); MBARRIER_INVAL(sb + SM_EPI(i)); }
    }
    if (wid == 9) TCGEN05_DEALLOC(tbase, 512);
#endif  // HAS_TCG
}

// ---------------------------------------------------------------------------
// Fallback main (non-103a passes): R1 popcount kernel.
// ---------------------------------------------------------------------------
__global__ __launch_bounds__(256) void abc_popc_kernel(
    const float* __restrict__ alphas, float* __restrict__ out) {
#if !HAS_TCG
    extern __shared__ unsigned skb[];
    float* sa = reinterpret_cast<float*>(skb + KWORDS);
    for (int i = threadIdx.x; i < KWORDS; i += blockDim.x) skb[i] = g_kbits[i];
    for (int i = threadIdx.x; i < EE * FF; i += blockDim.x) sa[i] = alphas[i];
    __syncthreads();

    const float inv_d = 1.0f / (float)DD;
    for (int pid = blockIdx.x * blockDim.x + threadIdx.x; pid < NPIX_OUT;
         pid += gridDim.x * blockDim.x) {
        int ow  = pid % OW;
        int tmp = pid / OW;
        int oh  = tmp % OH;
        int b   = tmp / OH;
        uint4 win[9];
        float ssum = 0.f;
        #pragma unroll
        for (int dy = 0; dy < 3; dy++)
            #pragma unroll
            for (int dx = 0; dx < 3; dx++) {
                int p = (b * HH + oh + dy) * WW + (ow + dx);
                win[dy * 3 + dx] = reinterpret_cast<const uint4*>(g_xbits)[p];
                ssum += g_S[p];
            }
        float beta = ssum * inv_d;
        size_t obase = (size_t)pid * FF;
        for (int f0 = 0; f0 < FF; f0 += 4) {
            float4 r;
            #pragma unroll
            for (int fi = 0; fi < 4; fi++) {
                int f = f0 + fi;
                const uint4* kb = reinterpret_cast<const uint4*>(skb + f * (EE * 9 * CWRD));
                int p0 = 0, p1 = 0, p2 = 0;
                #pragma unroll
                for (int t = 0; t < 9; t++) {
                    uint4 xv = win[t];
                    uint4 k0 = kb[t], k1 = kb[9 + t], k2 = kb[18 + t];
                    p0 += __popc(xv.x ^ k0.x) + __popc(xv.y ^ k0.y) + __popc(xv.z ^ k0.z) + __popc(xv.w ^ k0.w);
                    p1 += __popc(xv.x ^ k1.x) + __popc(xv.y ^ k1.y) + __popc(xv.z ^ k1.z) + __popc(xv.w ^ k1.w);
                    p2 += __popc(xv.x ^ k2.x) + __popc(xv.y ^ k2.y) + __popc(xv.z ^ k2.z) + __popc(xv.w ^ k2.w);
                }
                float val = sa[f] * (float)(DD - 2 * p0) + sa[FF + f] * (float)(DD - 2 * p1)
                          + sa[2 * FF + f] * (float)(DD - 2 * p2);
                (&r.x)[fi] = beta * val;
            }
            *reinterpret_cast<float4*>(out + obase + f0) = r;
        }
    }
#endif  // !HAS_TCG
}

// ---------------------------------------------------------------------------
extern "C" void kernel_launch(void* const* d_in, const int* in_sizes, int n_in,
                              void* d_out, int out_size) {
    const float* x = (const float*)d_in[0];
    const float* k = (const float*)d_in[1];
    const float* a = (const float*)d_in[2];
    float* out = (float*)d_out;

    binarize_kernel<<<NPIX_IN / 8, 256>>>(x);
    wpack_kernel<<<(9 * CINC * FF) / 256, 256>>>(k, a);
    kpack_kernel<<<KWORDS / 8, 256>>>(k);
    beta_kernel<<<(NPIX_OUT + 255) / 256, 256>>>();

    cudaFuncSetAttribute(abc_mma2_kernel,
                         cudaFuncAttributeMaxDynamicSharedMemorySize, SMEM_TOT);
    cudaFuncSetAttribute(abc_popc_kernel,
                         cudaFuncAttributeMaxDynamicSharedMemorySize, POPC_SMEM);
    abc_popc_kernel<<<296, 256, POPC_SMEM>>>(a, out);
    abc_mma2_kernel<<<BB * 8, NTHREADS, SMEM_TOT>>>(out);
}

// round 11
// speedup vs baseline: 7.3448x; 1.0358x over previous
#include <cuda_runtime.h>
#include <cuda_fp16.h>
#include <cstdint>

// ---------------- problem constants ----------------
#define BB 16
#define HH 112
#define WW 112
#define CINC 128
#define FF 256
#define EE 3
#define OH 110
#define OW 110
#define NPIX_IN  (BB * HH * WW)
#define NPIX_OUT (BB * OH * OW)
#define DD 1152
#define CWRD 4
#define NJOBS (128 * OH)                    // 14080 (b,fs,row) jobs
#define NCTA  148

#if defined(__CUDA_ARCH__) && defined(__CUDA_ARCH_FEAT_SM103_ALL)
#define HAS_TCG 1
#else
#define HAS_TCG 0
#endif

// A row buffer: 112 px x 128 ch fp16, blocked SW128 atoms, cc stride 14336B.
#define RB 28672
// B tile (per dy): 96 n-rows (n = dx*32+f) x 128 ch fp16, blocked SW128,
// cc chunk stride 12288B. 24576B per tile, 3 tiles per filter slice.
#define BT 24576
#define NA 5                                // A ring slots
#define NTHREADS 320                        // 8 epi + 1 producer + 1 mma warps

// smem layout (main kernel)
#define SM_TMEM   0
#define SM_BBAR   64
#define SM_BEMPTY 96
#define SM_FULL(i)  (128 + (i) * 16)
#define SM_EMPTY(i) (224 + (i) * 16)
#define SM_ACC(p)   (320 + (p) * 16)
#define SM_EPI(p)   (384 + (p) * 16)
#define SMEM_A    1024
#define SMEM_B    (SMEM_A + NA * RB)        // 144384 (1024-aligned)
#define ST_D1     (SMEM_B + 3 * BT)         // 218112; 4 x 128 floats
#define ST_D2     (ST_D1 + 4 * 128 * 4)     // 220160; 4 x 256 floats
#define SMEM_TOT  (ST_D2 + 4 * 256 * 4 + 64)  // 224320

// popc fallback smem
#define KWORDS (FF * EE * 9 * CWRD)
#define POPC_SMEM ((KWORDS + EE * FF) * 4)

// idesc: kind::f16 fp16 inputs, fp32 accum, M=128, N=96
#define MMA_IDESC ((1u << 4) | ((96 / 8) << 17) | ((128 / 16) << 24))

// ---------------- scratch (device globals) ----------------
__device__ __align__(1024) unsigned char g_xq[(size_t)BB * HH * RB + 32768];
__device__ __align__(1024) unsigned char g_w[(size_t)8 * 3 * BT];
__device__ float    g_S[NPIX_IN];
__device__ float    g_beta[NPIX_OUT];
__device__ unsigned g_xbits[NPIX_IN * CWRD];
__device__ unsigned g_kbits[KWORDS];

// ---------------- generic PTX helpers ----------------
__device__ __forceinline__ uint32_t smem_u32(const void* p) {
    uint32_t a;
    asm("{ .reg .u64 t; cvta.to.shared.u64 t, %1; cvt.u32.u64 %0, t; }" : "=r"(a) : "l"(p));
    return a;
}
__device__ __forceinline__ uint32_t elect_one() {
    uint32_t pred;
    asm volatile("{\n\t.reg .pred p;\n\telect.sync _|p, 0xFFFFFFFF;\n\tselp.b32 %0, 1, 0, p;\n\t}" : "=r"(pred));
    return pred;
}
#define MBARRIER_INIT(a, c) \
    asm volatile("mbarrier.init.shared.b64 [%0], %1;" :: "r"((uint32_t)(a)), "r"((uint32_t)(c)) : "memory")
#define MBARRIER_EXPECT_TX(a, b) \
    asm volatile("mbarrier.arrive.expect_tx.shared.b64 _, [%0], %1;" :: "r"((uint32_t)(a)), "r"((uint32_t)(b)) : "memory")
#define MBARRIER_ARRIVE(a) \
    asm volatile("mbarrier.arrive.shared.b64 _, [%0];" :: "r"((uint32_t)(a)) : "memory")
#define MBARRIER_INVAL(a) \
    asm volatile("mbarrier.inval.shared.b64 [%0];" :: "r"((uint32_t)(a)) : "memory")
#define MBARRIER_WAIT(a, par) do {                                           \
    uint32_t _m = (uint32_t)(a); uint32_t _p = (uint32_t)(par);              \
    asm volatile("{\n\t.reg .pred P1;\n\t"                                   \
        "WAIT_LP_%=:\n\t"                                                    \
        "mbarrier.try_wait.parity.acquire.cta.shared::cta.b64 P1, [%0], %1, 0x989680;\n\t" \
        "@P1 bra.uni WAIT_DN_%=;\n\t"                                        \
        "bra.uni WAIT_LP_%=;\n\t"                                            \
        "WAIT_DN_%=:\n\t}" :: "r"(_m), "r"(_p) : "memory");                  \
} while (0)
#define BULK_G2S(dst, src, bytes, mbar) \
    asm volatile("cp.async.bulk.shared::cluster.global.mbarrier::complete_tx::bytes [%0], [%1], %2, [%3];" \
        :: "r"((uint32_t)(dst)), "l"(src), "r"((uint32_t)(bytes)), "r"((uint32_t)(mbar)) : "memory")

// ---------------- tcgen05 helpers (sm_103a only) ----------------
#if HAS_TCG
#define TCGEN05_ALLOC(sa, n) \
    asm volatile("tcgen05.alloc.cta_group::1.sync.aligned.shared::cta.b32 [%0], %1;" \
        :: "r"((uint32_t)(sa)), "r"((uint32_t)(n)) : "memory")
#define TCGEN05_DEALLOC(t, n) \
    asm volatile("tcgen05.dealloc.cta_group::1.sync.aligned.b32 %0, %1;" :: "r"(t), "r"((uint32_t)(n)))
#define TCGEN05_RELINQ() \
    asm volatile("tcgen05.relinquish_alloc_permit.cta_group::1.sync.aligned;")
#define TCGEN05_COMMIT(mb) \
    asm volatile("tcgen05.commit.cta_group::1.mbarrier::arrive::one.shared::cluster.b64 [%0];" \
        :: "r"((uint32_t)(mb)) : "memory")
#define TCGEN05_FENCE_AFTER()  asm volatile("tcgen05.fence::after_thread_sync;" ::: "memory")
#define TCGEN05_FENCE_BEFORE() asm volatile("tcgen05.fence::before_thread_sync;" ::: "memory")
#define TCGEN05_WAIT_LD()      asm volatile("tcgen05.wait::ld.sync.aligned;" ::: "memory")

#define TCGEN05_LD_X32(r, ta)                                                 \
    asm volatile("tcgen05.ld.sync.aligned.32x32b.x32.b32 "                    \
        "{%0, %1, %2, %3, %4, %5, %6, %7, %8, %9, %10, %11, %12, %13, %14, %15, " \
        " %16, %17, %18, %19, %20, %21, %22, %23, %24, %25, %26, %27, %28, %29, %30, %31}, [%32];" \
        : "=r"((r)[0]), "=r"((r)[1]), "=r"((r)[2]), "=r"((r)[3]),             \
          "=r"((r)[4]), "=r"((r)[5]), "=r"((r)[6]), "=r"((r)[7]),             \
          "=r"((r)[8]), "=r"((r)[9]), "=r"((r)[10]), "=r"((r)[11]),           \
          "=r"((r)[12]), "=r"((r)[13]), "=r"((r)[14]), "=r"((r)[15]),         \
          "=r"((r)[16]), "=r"((r)[17]), "=r"((r)[18]), "=r"((r)[19]),         \
          "=r"((r)[20]), "=r"((r)[21]), "=r"((r)[22]), "=r"((r)[23]),         \
          "=r"((r)[24]), "=r"((r)[25]), "=r"((r)[26]), "=r"((r)[27]),         \
          "=r"((r)[28]), "=r"((r)[29]), "=r"((r)[30]), "=r"((r)[31])          \
        : "r"(ta))

__device__ __forceinline__ void mma_f16_ss(uint32_t d, uint64_t adesc, uint64_t bdesc,
                                           uint32_t idesc, uint32_t en) {
    asm volatile(
        "{\n\t.reg .pred p;\n\tsetp.ne.u32 p, %5, 0;\n\t"
        "tcgen05.mma.cta_group::1.kind::f16 [%0], %1, %2, %3, {%4, %4, %4, %4}, p;\n\t}"
        :: "r"(d), "l"(adesc), "l"(bdesc), "r"(idesc), "r"(0u), "r"(en) : "memory");
}

// SW128 K-major descriptor, 1024-aligned bases only.
__device__ __forceinline__ uint64_t make_desc(uint32_t addr) {
    return (uint64_t(2) << 61) | (uint64_t(1) << 46) | (uint64_t(64) << 32) | (uint64_t(1) << 16)
         | ((uint64_t)((addr >> 4) & 0x3FFF));
}
#endif  // HAS_TCG

// ---------------------------------------------------------------------------
// Prep 1: binarize x; one warp per input pixel. Always computes g_S.
// ---------------------------------------------------------------------------
__global__ __launch_bounds__(256) void binarize_kernel(const float* __restrict__ x) {
    int warp = (blockIdx.x * 256 + threadIdx.x) >> 5;
    int lane = threadIdx.x & 31;
    if (warp >= NPIX_IN) return;

    const float4 v = reinterpret_cast<const float4*>(x + (size_t)warp * CINC)[lane];
    float s = fabsf(v.x) + fabsf(v.y) + fabsf(v.z) + fabsf(v.w);
    #pragma unroll
    for (int off = 16; off > 0; off >>= 1) s += __shfl_xor_sync(0xFFFFFFFFu, s, off);
    if (lane == 0) g_S[warp] = s;

#if HAS_TCG
    unsigned h01 = (v.x >= 0.f ? 0x3C00u : 0xBC00u) | ((v.y >= 0.f ? 0x3C00u : 0xBC00u) << 16);
    unsigned h23 = (v.z >= 0.f ? 0x3C00u : 0xBC00u) | ((v.w >= 0.f ? 0x3C00u : 0xBC00u) << 16);
    int w  = warp % WW;
    int ro = warp / WW;
    int c  = lane * 4;
    unsigned o = (unsigned)(c >> 6) * 14336 + (unsigned)w * 128 + (c & 63) * 2;
    unsigned swz = o ^ ((o >> 3) & 0x70);
    *reinterpret_cast<uint2*>(g_xq + (size_t)ro * RB + swz) = make_uint2(h01, h23);
#else
    unsigned nib = (v.x >= 0.f ? 1u : 0u) | (v.y >= 0.f ? 2u : 0u)
                 | (v.z >= 0.f ? 4u : 0u) | (v.w >= 0.f ? 8u : 0u);
    unsigned wv = nib << (4 * (lane & 7));
    wv |= __shfl_xor_sync(0xFFFFFFFFu, wv, 1);
    wv |= __shfl_xor_sync(0xFFFFFFFFu, wv, 2);
    wv |= __shfl_xor_sync(0xFFFFFFFFu, wv, 4);
    if ((lane & 7) == 0) g_xbits[warp * CWRD + (lane >> 3)] = wv;
#endif
}

// ---------------------------------------------------------------------------
// Prep 2a (sm_103a): Wc[tap,c,f] = sum_e alpha[e,f]*sign(K[e,tap,c,f]), fp16.
// Per filter-slice fs: 3 tiles (dy); tile rows n = dx*32 + (f&31), 128 ch,
// blocked SW128 (cc chunk stride 12288B).
// ---------------------------------------------------------------------------
__global__ __launch_bounds__(256) void wpack_kernel(const float* __restrict__ k,
                                                    const float* __restrict__ alphas) {
#if HAS_TCG
    int tid = blockIdx.x * 256 + threadIdx.x;
    if (tid >= 9 * CINC * FF) return;
    int f = tid & 255;
    int c = (tid >> 8) & 127;
    int tap = tid >> 15;              // 0..8, = dy*3+dx
    int dy = tap / 3, dx = tap % 3;

    float wc = 0.f;
    #pragma unroll
    for (int e = 0; e < EE; e++) {
        float kv = k[(((size_t)e * 9 + tap) * CINC + c) * FF + f];
        float a  = alphas[e * FF + f];
        wc += (kv >= 0.f) ? a : -a;
    }
    int fs = f >> 5;
    int n  = dx * 32 + (f & 31);      // row within N=96 tile
    unsigned o = (unsigned)(c >> 6) * 12288 + (unsigned)n * 128 + (c & 63) * 2;
    unsigned swz = o ^ ((o >> 3) & 0x70);
    *reinterpret_cast<unsigned short*>(g_w + (size_t)(fs * 3 + dy) * BT + swz) =
        __half_as_ushort(__float2half_rn(wc));
#endif
}

// Prep 2b (fallback): packed kernel sign bits.
__global__ __launch_bounds__(256) void kpack_kernel(const float* __restrict__ k) {
#if !HAS_TCG
    int idx  = (blockIdx.x * blockDim.x + threadIdx.x) >> 5;
    int lane = threadIdx.x & 31;
    if (idx >= KWORDS) return;
    int w   = idx & (CWRD - 1);
    int t3  = idx >> 2;
    int tap = t3 % 9;
    int fe  = t3 / 9;
    int e   = fe % EE;
    int f   = fe / EE;
    int c   = w * 32 + lane;
    float val = k[((size_t)(e * 9 + tap) * CINC + c) * FF + f];
    unsigned bits = __ballot_sync(0xFFFFFFFFu, val >= 0.f);
    if (lane == 0) g_kbits[idx] = bits;
#endif
}

// Prep 3 (sm_103a): beta image.
__global__ __launch_bounds__(256) void beta_kernel() {
#if HAS_TCG
    int pid = blockIdx.x * 256 + threadIdx.x;
    if (pid >= NPIX_OUT) return;
    int ow = pid % OW;
    int t  = pid / OW;
    int oh = t % OH;
    int b  = t / OH;
    float s = 0.f;
    #pragma unroll
    for (int dy = 0; dy < 3; dy++)
        #pragma unroll
        for (int dx = 0; dx < 3; dx++)
            s += g_S[(b * HH + oh + dy) * WW + (ow + dx)];
    g_beta[pid] = s * (1.0f / (float)DD);
#endif
}

// ---------------------------------------------------------------------------
// Main (sm_103a): PERSISTENT implicit-GEMM conv, 148 CTAs (1 per SM, 2 per
// tensor-unit pair -> balanced tensor load). Jobs j in [0,14080):
// j -> (seg = j/110 -> b=seg>>3, fs=seg&7; oh = j%110). CTA i handles
// [i*J/148, (i+1)*J/148) (~95 rows, <=2 segments; B reloaded per segment).
// Per job ONE N=96 accumulator (cols = dx*32+f), 24 dispatches, 1 commit;
// dx applied by lane shift in the epilogue. A rows in 5-slot ring with
// phases carried across segments. TMEM pipeline p = jj&3. Two epilogue
// warp-groups by job parity. Warp 8 producer, warp 9 MMA.
// ---------------------------------------------------------------------------
__global__ __launch_bounds__(NTHREADS, 1) void abc_mma3_kernel(float* __restrict__ out) {
#if HAS_TCG
    extern __shared__ char smem[];
    const uint32_t sb = smem_u32(smem);
    const int tid = threadIdx.x;
    const int wid = tid >> 5;
    const int lane = tid & 31;

    const int jstart = (int)(((long long)blockIdx.x * NJOBS) / NCTA);
    const int jend   = (int)(((long long)(blockIdx.x + 1) * NJOBS) / NCTA);
    const int njobs  = jend - jstart;

    if (tid == 0) {
        MBARRIER_INIT(sb + SM_BBAR, 1);
        MBARRIER_INIT(sb + SM_BEMPTY, 1);
        #pragma unroll
        for (int i = 0; i < NA; i++) {
            MBARRIER_INIT(sb + SM_FULL(i), 1);
            MBARRIER_INIT(sb + SM_EMPTY(i), 1);
        }
        #pragma unroll
        for (int i = 0; i < 4; i++) {
            MBARRIER_INIT(sb + SM_ACC(i), 1);
            MBARRIER_INIT(sb + SM_EPI(i), 4);
        }
    }
    if (wid == 9) { TCGEN05_ALLOC(sb + SM_TMEM, 512); TCGEN05_RELINQ(); }
    __syncthreads();
    uint32_t tbase;
    asm volatile("ld.shared.b32 %0, [%1];" : "=r"(tbase) : "r"(sb + SM_TMEM));

    // ---------------- producer (warp 8) ----------------
    if (wid == 8) {
        if (elect_one()) {
            int eph[NA] = {0, 0, 0, 0, 0};
            int lp = 0;                    // loaded-row counter (global)
            int seg_idx = 0;
            for (int j = jstart; j < jend; ) {
                int seg = j / OH;
                int b = seg >> 3, fs = seg & 7;
                int r0 = j % OH;
                int segend = (seg + 1) * OH; if (segend > jend) segend = jend;
                int r1 = r0 + (segend - j);        // output rows [r0, r1)
                // B tiles for this segment
                if (seg_idx > 0) MBARRIER_WAIT(sb + SM_BEMPTY, (seg_idx - 1) & 1);
                MBARRIER_EXPECT_TX(sb + SM_BBAR, 3 * BT);
                #pragma unroll
                for (int t = 0; t < 3; t++)
                    BULK_G2S(sb + SMEM_B + t * BT, g_w + (size_t)(fs * 3 + t) * BT, BT, sb + SM_BBAR);
                // A input rows [r0, r1+2)
                for (int r = r0; r < r1 + 2; r++) {
                    int s = lp % NA;
                    if (lp >= NA) { MBARRIER_WAIT(sb + SM_EMPTY(s), eph[s]); eph[s] ^= 1; }
                    MBARRIER_EXPECT_TX(sb + SM_FULL(s), RB);
                    BULK_G2S(sb + SMEM_A + s * RB, g_xq + (size_t)(b * HH + r) * RB, RB, sb + SM_FULL(s));
                    lp++;
                }
                seg_idx++;
                j = segend;
            }
        }
    }

    // ---------------- MMA (warp 9) ----------------
    if (wid == 9) {
        // K-step descriptor offsets (16B units): A cc1 at +14336B, B cc1 at +12288B
        const uint32_t akoff[8] = {0, 2, 4, 6, 896, 898, 900, 902};
        const uint32_t bkoff[8] = {0, 2, 4, 6, 768, 770, 772, 774};
        int fph[NA] = {0, 0, 0, 0, 0};
        int Lw = 0;                        // next loaded-row index to wait on
        int Lbase = 0;                     // loaded rows before current segment
        int jj = 0;                        // local job counter
        int seg_idx = 0;
        for (int j = jstart; j < jend; ) {
            int seg = j / OH;
            int segend = (seg + 1) * OH; if (segend > jend) segend = jend;
            int n = segend - j;
            MBARRIER_WAIT(sb + SM_BBAR, seg_idx & 1);
            for (int r = 0; r < n; r++, jj++) {
                while (Lw <= Lbase + r + 2) {
                    int s = Lw % NA;
                    MBARRIER_WAIT(sb + SM_FULL(s), fph[s]); fph[s] ^= 1;
                    Lw++;
                }
                if (jj >= 4) MBARRIER_WAIT(sb + SM_EPI(jj & 3), ((jj >> 2) - 1) & 1);
                TCGEN05_FENCE_AFTER();
                if (elect_one()) {
                    uint32_t dacc = tbase + (jj & 3) * 96;
                    #pragma unroll
                    for (int dy = 0; dy < 3; dy++) {
                        int sl = (Lbase + r + dy) % NA;
                        uint64_t ad = make_desc(sb + SMEM_A + sl * RB);
                        uint64_t bd = make_desc(sb + SMEM_B + dy * BT);
                        #pragma unroll
                        for (int k = 0; k < 8; k++)
                            mma_f16_ss(dacc, ad + akoff[k], bd + bkoff[k], MMA_IDESC,
                                       !(dy == 0 && k == 0));
                    }
                    TCGEN05_COMMIT(sb + SM_EMPTY((Lbase + r) % NA));
                    TCGEN05_COMMIT(sb + SM_ACC(jj & 3));
                }
            }
            // release the 2 trailing input rows + B buffer of this segment
            if (elect_one()) {
                TCGEN05_COMMIT(sb + SM_EMPTY((Lbase + n) % NA));
                TCGEN05_COMMIT(sb + SM_EMPTY((Lbase + n + 1) % NA));
                TCGEN05_COMMIT(sb + SM_BEMPTY);
            }
            Lbase += n + 2;
            seg_idx++;
            j = segend;
        }
    }

    // ---------------- epilogue (warps 0-7, two groups by job parity) --------
    if (wid < 8) {
        const int g  = wid >> 2;           // group: 0 = even jobs, 1 = odd jobs
        const int lw = wid & 3;            // warp within group
        float* sD1 = reinterpret_cast<float*>(smem + ST_D1);
        float* sD2 = reinterpret_cast<float*>(smem + ST_D2);
        for (int jj = g; jj < njobs; jj += 2) {
            int j = jstart + jj;
            int seg = j / OH;
            int b = seg >> 3, fs = seg & 7;
            int oh = j % OH;
            int p = jj & 3;
            int q = g * 2 + ((jj >> 1) & 1);   // staging buffer index (4 sets)
            MBARRIER_WAIT(sb + SM_ACC(p), (jj >> 2) & 1);
            TCGEN05_FENCE_AFTER();
            uint32_t r0[32], r1[32], r2[32];
            TCGEN05_LD_X32(r0, tbase + p * 96);
            TCGEN05_LD_X32(r1, tbase + p * 96 + 32);
            TCGEN05_LD_X32(r2, tbase + p * 96 + 64);
            TCGEN05_WAIT_LD();
            TCGEN05_FENCE_BEFORE();
            if (elect_one()) MBARRIER_ARRIVE(sb + SM_EPI(p));  // free accumulator early

            if (lw > 0 && lane < 2) {
                #pragma unroll
                for (int jr = 0; jr < 32; jr++) {
                    if (lane == 0) sD1[q * 128 + lw * 32 + jr] = __uint_as_float(r1[jr]);
                    sD2[q * 256 + (lw * 2 + lane) * 32 + jr] = __uint_as_float(r2[jr]);
                }
            }
            asm volatile("bar.sync %0, 128;" :: "r"(1 + g) : "memory");

            int ow = lw * 32 + lane;
            bool valid = (ow < OW);
            float beta = 0.f;
            int pid = 0;
            if (valid) {
                pid = (b * OH + oh) * OW + ow;
                beta = g_beta[pid];
            }
            float v[32];
            #pragma unroll
            for (int jr = 0; jr < 32; jr++) {
                float f0 = __uint_as_float(r0[jr]);
                float f1 = __uint_as_float(__shfl_down_sync(0xFFFFFFFFu, r1[jr], 1));
                float f2 = __uint_as_float(__shfl_down_sync(0xFFFFFFFFu, r2[jr], 2));
                if (lane == 31 && lw < 3) f1 = sD1[q * 128 + (lw + 1) * 32 + jr];
                if (lane >= 30 && lw < 3) f2 = sD2[q * 256 + ((lw + 1) * 2 + (lane - 30)) * 32 + jr];
                v[jr] = beta * (f0 + f1 + f2);
            }
            if (valid) {
                float* ob = out + (size_t)pid * FF + fs * 32;
                #pragma unroll
                for (int qq = 0; qq < 8; qq++)
                    *reinterpret_cast<float4*>(ob + qq * 4) =
                        make_float4(v[qq * 4], v[qq * 4 + 1], v[qq * 4 + 2], v[qq * 4 + 3]);
            }
        }
    }

    __syncthreads();
    if (tid == 0) {
        MBARRIER_INVAL(sb + SM_BBAR);
        MBARRIER_INVAL(sb + SM_BEMPTY);
        #pragma unroll
        for (int i = 0; i < NA; i++) { MBARRIER_INVAL(sb + SM_FULL(i)); MBARRIER_INVAL(sb + SM_EMPTY(i)); }
        #pragma unroll
        for (int i = 0; i < 4; i++) { MBARRIER_INVAL(sb + SM_ACC(i)); MBARRIER_INVAL(sb + SM_EPI(i)); }
    }
    if (wid == 9) TCGEN05_DEALLOC(tbase, 512);
#endif  // HAS_TCG
}

// ---------------------------------------------------------------------------
// Fallback main (non-103a passes): R1 popcount kernel.
// ---------------------------------------------------------------------------
__global__ __launch_bounds__(256) void abc_popc_kernel(
    const float* __restrict__ alphas, float* __restrict__ out) {
#if !HAS_TCG
    extern __shared__ unsigned skb[];
    float* sa = reinterpret_cast<float*>(skb + KWORDS);
    for (int i = threadIdx.x; i < KWORDS; i += blockDim.x) skb[i] = g_kbits[i];
    for (int i = threadIdx.x; i < EE * FF; i += blockDim.x) sa[i] = alphas[i];
    __syncthreads();

    const float inv_d = 1.0f / (float)DD;
    for (int pid = blockIdx.x * blockDim.x + threadIdx.x; pid < NPIX_OUT;
         pid += gridDim.x * blockDim.x) {
        int ow  = pid % OW;
        int tmp = pid / OW;
        int oh  = tmp % OH;
        int b   = tmp / OH;
        uint4 win[9];
        float ssum = 0.f;
        #pragma unroll
        for (int dy = 0; dy < 3; dy++)
            #pragma unroll
            for (int dx = 0; dx < 3; dx++) {
                int p = (b * HH + oh + dy) * WW + (ow + dx);
                win[dy * 3 + dx] = reinterpret_cast<const uint4*>(g_xbits)[p];
                ssum += g_S[p];
            }
        float beta = ssum * inv_d;
        size_t obase = (size_t)pid * FF;
        for (int f0 = 0; f0 < FF; f0 += 4) {
            float4 r;
            #pragma unroll
            for (int fi = 0; fi < 4; fi++) {
                int f = f0 + fi;
                const uint4* kb = reinterpret_cast<const uint4*>(skb + f * (EE * 9 * CWRD));
                int p0 = 0, p1 = 0, p2 = 0;
                #pragma unroll
                for (int t = 0; t < 9; t++) {
                    uint4 xv = win[t];
                    uint4 k0 = kb[t], k1 = kb[9 + t], k2 = kb[18 + t];
                    p0 += __popc(xv.x ^ k0.x) + __popc(xv.y ^ k0.y) + __popc(xv.z ^ k0.z) + __popc(xv.w ^ k0.w);
                    p1 += __popc(xv.x ^ k1.x) + __popc(xv.y ^ k1.y) + __popc(xv.z ^ k1.z) + __popc(xv.w ^ k1.w);
                    p2 += __popc(xv.x ^ k2.x) + __popc(xv.y ^ k2.y) + __popc(xv.z ^ k2.z) + __popc(xv.w ^ k2.w);
                }
                float val = sa[f] * (float)(DD - 2 * p0) + sa[FF + f] * (float)(DD - 2 * p1)
                          + sa[2 * FF + f] * (float)(DD - 2 * p2);
                (&r.x)[fi] = beta * val;
            }
            *reinterpret_cast<float4*>(out + obase + f0) = r;
        }
    }
#endif  // !HAS_TCG
}

// ---------------------------------------------------------------------------
extern "C" void kernel_launch(void* const* d_in, const int* in_sizes, int n_in,
                              void* d_out, int out_size) {
    const float* x = (const float*)d_in[0];
    const float* k = (const float*)d_in[1];
    const float* a = (const float*)d_in[2];
    float* out = (float*)d_out;

    binarize_kernel<<<NPIX_IN / 8, 256>>>(x);
    wpack_kernel<<<(9 * CINC * FF) / 256, 256>>>(k, a);
    kpack_kernel<<<KWORDS / 8, 256>>>(k);
    beta_kernel<<<(NPIX_OUT + 255) / 256, 256>>>();

    cudaFuncSetAttribute(abc_mma3_kernel,
                         cudaFuncAttributeMaxDynamicSharedMemorySize, SMEM_TOT);
    cudaFuncSetAttribute(abc_popc_kernel,
                         cudaFuncAttributeMaxDynamicSharedMemorySize, POPC_SMEM);
    abc_popc_kernel<<<296, 256, POPC_SMEM>>>(a, out);
    abc_mma3_kernel<<<NCTA, NTHREADS, SMEM_TOT>>>(out);
}

// round 14
// speedup vs baseline: 7.5470x; 1.0275x over previous
#include <cuda_runtime.h>
#include <cuda_fp16.h>
#include <cstdint>

// ---------------- problem constants ----------------
#define BB 16
#define HH 112
#define WW 112
#define CINC 128
#define FF 256
#define EE 3
#define OH 110
#define OW 110
#define OH2 55                              // super-rows (2 output rows each)
#define NPIX_IN  (BB * HH * WW)
#define NPIX_OUT (BB * OH * OW)
#define DD 1152
#define CWRD 4
#define NSUP (128 * OH2)                    // 7040 super-jobs
#define NCTA  148

#if defined(__CUDA_ARCH__) && defined(__CUDA_ARCH_FEAT_SM103_ALL)
#define HAS_TCG 1
#else
#define HAS_TCG 0
#endif

// A row buffer: 112 px x 128 ch fp16, blocked SW128 atoms, cc stride 14336B.
#define RB 28672
// B tile (per dy): 96 n-rows (n = dx*32+f) x 128 ch fp16, blocked SW128,
// cc chunk stride 12288B. 24576B per tile, 3 tiles per filter slice.
#define BT 24576
#define NA 5                                // A ring slots
#define NTHREADS 320                        // 8 epi + 1 producer + 1 mma warps

// smem layout (main kernel)
#define SM_TMEM   0
#define SM_BBAR   64
#define SM_BEMPTY 96
#define SM_FULL(i)  (128 + (i) * 16)
#define SM_EMPTY(i) (224 + (i) * 16)
#define SM_ACC(p)   (320 + (p) * 16)
#define SM_EPI(p)   (384 + (p) * 16)
#define SMEM_A    1024
#define SMEM_B    (SMEM_A + NA * RB)        // 144384 (1024-aligned)
#define ST_D1     (SMEM_B + 3 * BT)         // 218112; 4 x 128 floats
#define ST_D2     (ST_D1 + 4 * 128 * 4)     // 220160; 4 x 256 floats
#define SMEM_TOT  (ST_D2 + 4 * 256 * 4 + 64)  // 224320

// popc fallback smem
#define KWORDS (FF * EE * 9 * CWRD)
#define POPC_SMEM ((KWORDS + EE * FF) * 4)

// idesc: kind::f16 fp16 inputs, fp32 accum, M=128, N=96
#define MMA_IDESC ((1u << 4) | ((96 / 8) << 17) | ((128 / 16) << 24))

// ---------------- scratch (device globals) ----------------
__device__ __align__(1024) unsigned char g_xq[(size_t)BB * HH * RB + 32768];
__device__ __align__(1024) unsigned char g_w[(size_t)8 * 3 * BT];
__device__ float    g_S[NPIX_IN];
__device__ float    g_beta[NPIX_OUT];
__device__ unsigned g_xbits[NPIX_IN * CWRD];
__device__ unsigned g_kbits[KWORDS];

// ---------------- generic PTX helpers ----------------
__device__ __forceinline__ uint32_t smem_u32(const void* p) {
    uint32_t a;
    asm("{ .reg .u64 t; cvta.to.shared.u64 t, %1; cvt.u32.u64 %0, t; }" : "=r"(a) : "l"(p));
    return a;
}
__device__ __forceinline__ uint32_t elect_one() {
    uint32_t pred;
    asm volatile("{\n\t.reg .pred p;\n\telect.sync _|p, 0xFFFFFFFF;\n\tselp.b32 %0, 1, 0, p;\n\t}" : "=r"(pred));
    return pred;
}
#define MBARRIER_INIT(a, c) \
    asm volatile("mbarrier.init.shared.b64 [%0], %1;" :: "r"((uint32_t)(a)), "r"((uint32_t)(c)) : "memory")
#define MBARRIER_EXPECT_TX(a, b) \
    asm volatile("mbarrier.arrive.expect_tx.shared.b64 _, [%0], %1;" :: "r"((uint32_t)(a)), "r"((uint32_t)(b)) : "memory")
#define MBARRIER_ARRIVE(a) \
    asm volatile("mbarrier.arrive.shared.b64 _, [%0];" :: "r"((uint32_t)(a)) : "memory")
#define MBARRIER_INVAL(a) \
    asm volatile("mbarrier.inval.shared.b64 [%0];" :: "r"((uint32_t)(a)) : "memory")
#define MBARRIER_WAIT(a, par) do {                                           \
    uint32_t _m = (uint32_t)(a); uint32_t _p = (uint32_t)(par);              \
    asm volatile("{\n\t.reg .pred P1;\n\t"                                   \
        "WAIT_LP_%=:\n\t"                                                    \
        "mbarrier.try_wait.parity.acquire.cta.shared::cta.b64 P1, [%0], %1, 0x989680;\n\t" \
        "@P1 bra.uni WAIT_DN_%=;\n\t"                                        \
        "bra.uni WAIT_LP_%=;\n\t"                                            \
        "WAIT_DN_%=:\n\t}" :: "r"(_m), "r"(_p) : "memory");                  \
} while (0)
#define BULK_G2S(dst, src, bytes, mbar) \
    asm volatile("cp.async.bulk.shared::cluster.global.mbarrier::complete_tx::bytes [%0], [%1], %2, [%3];" \
        :: "r"((uint32_t)(dst)), "l"(src), "r"((uint32_t)(bytes)), "r"((uint32_t)(mbar)) : "memory")

// ---------------- tcgen05 helpers (sm_103a only) ----------------
#if HAS_TCG
#define TCGEN05_ALLOC(sa, n) \
    asm volatile("tcgen05.alloc.cta_group::1.sync.aligned.shared::cta.b32 [%0], %1;" \
        :: "r"((uint32_t)(sa)), "r"((uint32_t)(n)) : "memory")
#define TCGEN05_DEALLOC(t, n) \
    asm volatile("tcgen05.dealloc.cta_group::1.sync.aligned.b32 %0, %1;" :: "r"(t), "r"((uint32_t)(n)))
#define TCGEN05_RELINQ() \
    asm volatile("tcgen05.relinquish_alloc_permit.cta_group::1.sync.aligned;")
#define TCGEN05_COMMIT(mb) \
    asm volatile("tcgen05.commit.cta_group::1.mbarrier::arrive::one.shared::cluster.b64 [%0];" \
        :: "r"((uint32_t)(mb)) : "memory")
#define TCGEN05_FENCE_AFTER()  asm volatile("tcgen05.fence::after_thread_sync;" ::: "memory")
#define TCGEN05_FENCE_BEFORE() asm volatile("tcgen05.fence::before_thread_sync;" ::: "memory")
#define TCGEN05_WAIT_LD()      asm volatile("tcgen05.wait::ld.sync.aligned;" ::: "memory")

#define TCGEN05_LD_X32(r, ta)                                                 \
    asm volatile("tcgen05.ld.sync.aligned.32x32b.x32.b32 "                    \
        "{%0, %1, %2, %3, %4, %5, %6, %7, %8, %9, %10, %11, %12, %13, %14, %15, " \
        " %16, %17, %18, %19, %20, %21, %22, %23, %24, %25, %26, %27, %28, %29, %30, %31}, [%32];" \
        : "=r"((r)[0]), "=r"((r)[1]), "=r"((r)[2]), "=r"((r)[3]),             \
          "=r"((r)[4]), "=r"((r)[5]), "=r"((r)[6]), "=r"((r)[7]),             \
          "=r"((r)[8]), "=r"((r)[9]), "=r"((r)[10]), "=r"((r)[11]),           \
          "=r"((r)[12]), "=r"((r)[13]), "=r"((r)[14]), "=r"((r)[15]),         \
          "=r"((r)[16]), "=r"((r)[17]), "=r"((r)[18]), "=r"((r)[19]),         \
          "=r"((r)[20]), "=r"((r)[21]), "=r"((r)[22]), "=r"((r)[23]),         \
          "=r"((r)[24]), "=r"((r)[25]), "=r"((r)[26]), "=r"((r)[27]),         \
          "=r"((r)[28]), "=r"((r)[29]), "=r"((r)[30]), "=r"((r)[31])          \
        : "r"(ta))

__device__ __forceinline__ void mma_f16_ss(uint32_t d, uint64_t adesc, uint64_t bdesc,
                                           uint32_t idesc, uint32_t en) {
    asm volatile(
        "{\n\t.reg .pred p;\n\tsetp.ne.u32 p, %5, 0;\n\t"
        "tcgen05.mma.cta_group::1.kind::f16 [%0], %1, %2, %3, {%4, %4, %4, %4}, p;\n\t}"
        :: "r"(d), "l"(adesc), "l"(bdesc), "r"(idesc), "r"(0u), "r"(en) : "memory");
}

// SW128 K-major descriptor, 1024-aligned bases only.
__device__ __forceinline__ uint64_t make_desc(uint32_t addr) {
    return (uint64_t(2) << 61) | (uint64_t(1) << 46) | (uint64_t(64) << 32) | (uint64_t(1) << 16)
         | ((uint64_t)((addr >> 4) & 0x3FFF));
}
#endif  // HAS_TCG

// ---------------------------------------------------------------------------
// Prep 1: binarize x; one warp per input pixel. Always computes g_S.
// ---------------------------------------------------------------------------
__global__ __launch_bounds__(256) void binarize_kernel(const float* __restrict__ x) {
    int warp = (blockIdx.x * 256 + threadIdx.x) >> 5;
    int lane = threadIdx.x & 31;
    if (warp >= NPIX_IN) return;

    const float4 v = reinterpret_cast<const float4*>(x + (size_t)warp * CINC)[lane];
    float s = fabsf(v.x) + fabsf(v.y) + fabsf(v.z) + fabsf(v.w);
    #pragma unroll
    for (int off = 16; off > 0; off >>= 1) s += __shfl_xor_sync(0xFFFFFFFFu, s, off);
    if (lane == 0) g_S[warp] = s;

#if HAS_TCG
    unsigned h01 = (v.x >= 0.f ? 0x3C00u : 0xBC00u) | ((v.y >= 0.f ? 0x3C00u : 0xBC00u) << 16);
    unsigned h23 = (v.z >= 0.f ? 0x3C00u : 0xBC00u) | ((v.w >= 0.f ? 0x3C00u : 0xBC00u) << 16);
    int w  = warp % WW;
    int ro = warp / WW;
    int c  = lane * 4;
    unsigned o = (unsigned)(c >> 6) * 14336 + (unsigned)w * 128 + (c & 63) * 2;
    unsigned swz = o ^ ((o >> 3) & 0x70);
    *reinterpret_cast<uint2*>(g_xq + (size_t)ro * RB + swz) = make_uint2(h01, h23);
#else
    unsigned nib = (v.x >= 0.f ? 1u : 0u) | (v.y >= 0.f ? 2u : 0u)
                 | (v.z >= 0.f ? 4u : 0u) | (v.w >= 0.f ? 8u : 0u);
    unsigned wv = nib << (4 * (lane & 7));
    wv |= __shfl_xor_sync(0xFFFFFFFFu, wv, 1);
    wv |= __shfl_xor_sync(0xFFFFFFFFu, wv, 2);
    wv |= __shfl_xor_sync(0xFFFFFFFFu, wv, 4);
    if ((lane & 7) == 0) g_xbits[warp * CWRD + (lane >> 3)] = wv;
#endif
}

// ---------------------------------------------------------------------------
// Prep 2a (sm_103a): Wc[tap,c,f] = sum_e alpha[e,f]*sign(K[e,tap,c,f]), fp16.
// Per filter-slice fs: 3 tiles (dy); tile rows n = dx*32 + (f&31), 128 ch,
// blocked SW128 (cc chunk stride 12288B).
// ---------------------------------------------------------------------------
__global__ __launch_bounds__(256) void wpack_kernel(const float* __restrict__ k,
                                                    const float* __restrict__ alphas) {
#if HAS_TCG
    int tid = blockIdx.x * 256 + threadIdx.x;
    if (tid >= 9 * CINC * FF) return;
    int f = tid & 255;
    int c = (tid >> 8) & 127;
    int tap = tid >> 15;              // 0..8, = dy*3+dx
    int dy = tap / 3, dx = tap % 3;

    float wc = 0.f;
    #pragma unroll
    for (int e = 0; e < EE; e++) {
        float kv = k[(((size_t)e * 9 + tap) * CINC + c) * FF + f];
        float a  = alphas[e * FF + f];
        wc += (kv >= 0.f) ? a : -a;
    }
    int fs = f >> 5;
    int n  = dx * 32 + (f & 31);      // row within N=96 tile
    unsigned o = (unsigned)(c >> 6) * 12288 + (unsigned)n * 128 + (c & 63) * 2;
    unsigned swz = o ^ ((o >> 3) & 0x70);
    *reinterpret_cast<unsigned short*>(g_w + (size_t)(fs * 3 + dy) * BT + swz) =
        __half_as_ushort(__float2half_rn(wc));
#endif
}

// Prep 2b (fallback): packed kernel sign bits.
__global__ __launch_bounds__(256) void kpack_kernel(const float* __restrict__ k) {
#if !HAS_TCG
    int idx  = (blockIdx.x * blockDim.x + threadIdx.x) >> 5;
    int lane = threadIdx.x & 31;
    if (idx >= KWORDS) return;
    int w   = idx & (CWRD - 1);
    int t3  = idx >> 2;
    int tap = t3 % 9;
    int fe  = t3 / 9;
    int e   = fe % EE;
    int f   = fe / EE;
    int c   = w * 32 + lane;
    float val = k[((size_t)(e * 9 + tap) * CINC + c) * FF + f];
    unsigned bits = __ballot_sync(0xFFFFFFFFu, val >= 0.f);
    if (lane == 0) g_kbits[idx] = bits;
#endif
}

// Prep 3 (sm_103a): beta image.
__global__ __launch_bounds__(256) void beta_kernel() {
#if HAS_TCG
    int pid = blockIdx.x * 256 + threadIdx.x;
    if (pid >= NPIX_OUT) return;
    int ow = pid % OW;
    int t  = pid / OW;
    int oh = t % OH;
    int b  = t / OH;
    float s = 0.f;
    #pragma unroll
    for (int dy = 0; dy < 3; dy++)
        #pragma unroll
        for (int dx = 0; dx < 3; dx++)
            s += g_S[(b * HH + oh + dy) * WW + (ow + dx)];
    g_beta[pid] = s * (1.0f / (float)DD);
#endif
}

// ---------------------------------------------------------------------------
// Main (sm_103a): PERSISTENT implicit-GEMM conv, 148 CTAs. SUPER-JOBS of 2
// output rows: sj in [0,7040), seg = sj/55 (b=seg>>3, fs=seg&7),
// oh0 = (sj%55)*2. CTA i handles [i*7040/148, (i+1)*7040/148) (<=2 segments).
// Per super-job: TMEM stage p = sjj&1 holds 192 cols (2 rows x N=96,
// cols = dx*32+f), 48 dispatches, split EMPTY commits (row 2r after m=0,
// 2r+1 after m=1) to keep the A producer ahead, ONE ACC commit. dx applied
// by lane shift in the epilogue. Two epilogue warp-groups alternate
// super-jobs; EPI released after the 2nd row's LDTM. Warp 8 prod, 9 MMA.
// ---------------------------------------------------------------------------
__global__ __launch_bounds__(NTHREADS, 1) void abc_mma4_kernel(float* __restrict__ out) {
#if HAS_TCG
    extern __shared__ char smem[];
    const uint32_t sb = smem_u32(smem);
    const int tid = threadIdx.x;
    const int wid = tid >> 5;
    const int lane = tid & 31;

    const int jstart = (int)(((long long)blockIdx.x * NSUP) / NCTA);
    const int jend   = (int)(((long long)(blockIdx.x + 1) * NSUP) / NCTA);
    const int njobs  = jend - jstart;

    if (tid == 0) {
        MBARRIER_INIT(sb + SM_BBAR, 1);
        MBARRIER_INIT(sb + SM_BEMPTY, 1);
        #pragma unroll
        for (int i = 0; i < NA; i++) {
            MBARRIER_INIT(sb + SM_FULL(i), 1);
            MBARRIER_INIT(sb + SM_EMPTY(i), 1);
        }
        #pragma unroll
        for (int i = 0; i < 2; i++) {
            MBARRIER_INIT(sb + SM_ACC(i), 1);
            MBARRIER_INIT(sb + SM_EPI(i), 4);
        }
    }
    if (wid == 9) { TCGEN05_ALLOC(sb + SM_TMEM, 512); TCGEN05_RELINQ(); }
    __syncthreads();
    uint32_t tbase;
    asm volatile("ld.shared.b32 %0, [%1];" : "=r"(tbase) : "r"(sb + SM_TMEM));

    // ---------------- producer (warp 8) ----------------
    if (wid == 8) {
        if (elect_one()) {
            int eph[NA] = {0, 0, 0, 0, 0};
            int lp = 0;                    // loaded-row counter (global)
            int seg_idx = 0;
            for (int j = jstart; j < jend; ) {
                int seg = j / OH2;
                int b = seg >> 3, fs = seg & 7;
                int r0 = j % OH2;
                int segend = (seg + 1) * OH2; if (segend > jend) segend = jend;
                int nrows = 2 * (segend - j) + 2;   // input rows [2r0, 2r0+nrows)
                if (seg_idx > 0) MBARRIER_WAIT(sb + SM_BEMPTY, (seg_idx - 1) & 1);
                MBARRIER_EXPECT_TX(sb + SM_BBAR, 3 * BT);
                #pragma unroll
                for (int t = 0; t < 3; t++)
                    BULK_G2S(sb + SMEM_B + t * BT, g_w + (size_t)(fs * 3 + t) * BT, BT, sb + SM_BBAR);
                for (int r = 0; r < nrows; r++) {
                    int s = lp % NA;
                    if (lp >= NA) { MBARRIER_WAIT(sb + SM_EMPTY(s), eph[s]); eph[s] ^= 1; }
                    MBARRIER_EXPECT_TX(sb + SM_FULL(s), RB);
                    BULK_G2S(sb + SMEM_A + s * RB,
                             g_xq + (size_t)(b * HH + 2 * r0 + r) * RB, RB, sb + SM_FULL(s));
                    lp++;
                }
                seg_idx++;
                j = segend;
            }
        }
    }

    // ---------------- MMA (warp 9) ----------------
    if (wid == 9) {
        // K-step descriptor offsets (16B units): A cc1 at +14336B, B cc1 at +12288B
        const uint32_t akoff[8] = {0, 2, 4, 6, 896, 898, 900, 902};
        const uint32_t bkoff[8] = {0, 2, 4, 6, 768, 770, 772, 774};
        int fph[NA] = {0, 0, 0, 0, 0};
        int Lw = 0;                        // next loaded-row index to wait on
        int Lbase = 0;                     // loaded rows before current segment
        int sjj = 0;                       // local super-job counter
        int seg_idx = 0;
        for (int j = jstart; j < jend; ) {
            int seg = j / OH2;
            int segend = (seg + 1) * OH2; if (segend > jend) segend = jend;
            int n = segend - j;
            MBARRIER_WAIT(sb + SM_BBAR, seg_idx & 1);
            for (int r = 0; r < n; r++, sjj++) {
                while (Lw <= Lbase + 2 * r + 3) {
                    int s = Lw % NA;
                    MBARRIER_WAIT(sb + SM_FULL(s), fph[s]); fph[s] ^= 1;
                    Lw++;
                }
                if (sjj >= 2) MBARRIER_WAIT(sb + SM_EPI(sjj & 1), ((sjj >> 1) - 1) & 1);
                TCGEN05_FENCE_AFTER();
                if (elect_one()) {
                    int p = sjj & 1;
                    #pragma unroll
                    for (int m = 0; m < 2; m++) {
                        uint32_t dacc = tbase + p * 192 + m * 96;
                        #pragma unroll
                        for (int dy = 0; dy < 3; dy++) {
                            int sl = (Lbase + 2 * r + m + dy) % NA;
                            uint64_t ad = make_desc(sb + SMEM_A + sl * RB);
                            uint64_t bd = make_desc(sb + SMEM_B + dy * BT);
                            #pragma unroll
                            for (int k = 0; k < 8; k++)
                                mma_f16_ss(dacc, ad + akoff[k], bd + bkoff[k], MMA_IDESC,
                                           !(dy == 0 && k == 0));
                        }
                        // free input row 2r+m as soon as its last reader is issued
                        TCGEN05_COMMIT(sb + SM_EMPTY((Lbase + 2 * r + m) % NA));
                    }
                    TCGEN05_COMMIT(sb + SM_ACC(p));
                }
            }
            // release the 2 trailing input rows + B buffer of this segment
            if (elect_one()) {
                TCGEN05_COMMIT(sb + SM_EMPTY((Lbase + 2 * n) % NA));
                TCGEN05_COMMIT(sb + SM_EMPTY((Lbase + 2 * n + 1) % NA));
                TCGEN05_COMMIT(sb + SM_BEMPTY);
            }
            Lbase += 2 * n + 2;
            seg_idx++;
            j = segend;
        }
    }

    // ---------------- epilogue (warps 0-7, two groups by super-job parity) --
    if (wid < 8) {
        const int g  = wid >> 2;           // group: 0 = even sj, 1 = odd sj
        const int lw = wid & 3;            // warp within group
        float* sD1 = reinterpret_cast<float*>(smem + ST_D1);
        float* sD2 = reinterpret_cast<float*>(smem + ST_D2);
        for (int sjj = g; sjj < njobs; sjj += 2) {
            int j = jstart + sjj;
            int seg = j / OH2;
            int b = seg >> 3, fs = seg & 7;
            int oh0 = (j % OH2) * 2;
            int p = sjj & 1;               // == g
            MBARRIER_WAIT(sb + SM_ACC(p), (sjj >> 1) & 1);
            TCGEN05_FENCE_AFTER();
            #pragma unroll
            for (int m = 0; m < 2; m++) {
                uint32_t r0[32], r1[32], r2[32];
                TCGEN05_LD_X32(r0, tbase + p * 192 + m * 96);
                TCGEN05_LD_X32(r1, tbase + p * 192 + m * 96 + 32);
                TCGEN05_LD_X32(r2, tbase + p * 192 + m * 96 + 64);
                TCGEN05_WAIT_LD();
                if (m == 1) {
                    TCGEN05_FENCE_BEFORE();
                    if (elect_one()) MBARRIER_ARRIVE(sb + SM_EPI(p));  // free stage
                }
                int q = g * 2 + m;         // staging buffer (4 sets)
                if (lw > 0 && lane < 2) {
                    #pragma unroll
                    for (int jr = 0; jr < 32; jr++) {
                        if (lane == 0) sD1[q * 128 + lw * 32 + jr] = __uint_as_float(r1[jr]);
                        sD2[q * 256 + (lw * 2 + lane) * 32 + jr] = __uint_as_float(r2[jr]);
                    }
                }
                asm volatile("bar.sync %0, 128;" :: "r"(1 + g) : "memory");

                int oh = oh0 + m;
                int ow = lw * 32 + lane;
                bool valid = (ow < OW);
                float beta = 0.f;
                int pid = 0;
                if (valid) {
                    pid = (b * OH + oh) * OW + ow;
                    beta = g_beta[pid];
                }
                float v[32];
                #pragma unroll
                for (int jr = 0; jr < 32; jr++) {
                    float f0 = __uint_as_float(r0[jr]);
                    float f1 = __uint_as_float(__shfl_down_sync(0xFFFFFFFFu, r1[jr], 1));
                    float f2 = __uint_as_float(__shfl_down_sync(0xFFFFFFFFu, r2[jr], 2));
                    if (lane == 31 && lw < 3) f1 = sD1[q * 128 + (lw + 1) * 32 + jr];
                    if (lane >= 30 && lw < 3) f2 = sD2[q * 256 + ((lw + 1) * 2 + (lane - 30)) * 32 + jr];
                    v[jr] = beta * (f0 + f1 + f2);
                }
                if (valid) {
                    float* ob = out + (size_t)pid * FF + fs * 32;
                    #pragma unroll
                    for (int qq = 0; qq < 8; qq++)
                        *reinterpret_cast<float4*>(ob + qq * 4) =
                            make_float4(v[qq * 4], v[qq * 4 + 1], v[qq * 4 + 2], v[qq * 4 + 3]);
                }
            }
        }
    }

    __syncthreads();
    if (tid == 0) {
        MBARRIER_INVAL(sb + SM_BBAR);
        MBARRIER_INVAL(sb + SM_BEMPTY);
        #pragma unroll
        for (int i = 0; i < NA; i++) { MBARRIER_INVAL(sb + SM_FULL(i)); MBARRIER_INVAL(sb + SM_EMPTY(i)); }
        #pragma unroll
        for (int i = 0; i < 2; i++) { MBARRIER_INVAL(sb + SM_ACC(i)); MBARRIER_INVAL(sb + SM_EPI(i)); }
    }
    if (wid == 9) TCGEN05_DEALLOC(tbase, 512);
#endif  // HAS_TCG
}

// ---------------------------------------------------------------------------
// Fallback main (non-103a passes): R1 popcount kernel.
// ---------------------------------------------------------------------------
__global__ __launch_bounds__(256) void abc_popc_kernel(
    const float* __restrict__ alphas, float* __restrict__ out) {
#if !HAS_TCG
    extern __shared__ unsigned skb[];
    float* sa = reinterpret_cast<float*>(skb + KWORDS);
    for (int i = threadIdx.x; i < KWORDS; i += blockDim.x) skb[i] = g_kbits[i];
    for (int i = threadIdx.x; i < EE * FF; i += blockDim.x) sa[i] = alphas[i];
    __syncthreads();

    const float inv_d = 1.0f / (float)DD;
    for (int pid = blockIdx.x * blockDim.x + threadIdx.x; pid < NPIX_OUT;
         pid += gridDim.x * blockDim.x) {
        int ow  = pid % OW;
        int tmp = pid / OW;
        int oh  = tmp % OH;
        int b   = tmp / OH;
        uint4 win[9];
        float ssum = 0.f;
        #pragma unroll
        for (int dy = 0; dy < 3; dy++)
            #pragma unroll
            for (int dx = 0; dx < 3; dx++) {
                int p = (b * HH + oh + dy) * WW + (ow + dx);
                win[dy * 3 + dx] = reinterpret_cast<const uint4*>(g_xbits)[p];
                ssum += g_S[p];
            }
        float beta = ssum * inv_d;
        size_t obase = (size_t)pid * FF;
        for (int f0 = 0; f0 < FF; f0 += 4) {
            float4 r;
            #pragma unroll
            for (int fi = 0; fi < 4; fi++) {
                int f = f0 + fi;
                const uint4* kb = reinterpret_cast<const uint4*>(skb + f * (EE * 9 * CWRD));
                int p0 = 0, p1 = 0, p2 = 0;
                #pragma unroll
                for (int t = 0; t < 9; t++) {
                    uint4 xv = win[t];
                    uint4 k0 = kb[t], k1 = kb[9 + t], k2 = kb[18 + t];
                    p0 += __popc(xv.x ^ k0.x) + __popc(xv.y ^ k0.y) + __popc(xv.z ^ k0.z) + __popc(xv.w ^ k0.w);
                    p1 += __popc(xv.x ^ k1.x) + __popc(xv.y ^ k1.y) + __popc(xv.z ^ k1.z) + __popc(xv.w ^ k1.w);
                    p2 += __popc(xv.x ^ k2.x) + __popc(xv.y ^ k2.y) + __popc(xv.z ^ k2.z) + __popc(xv.w ^ k2.w);
                }
                float val = sa[f] * (float)(DD - 2 * p0) + sa[FF + f] * (float)(DD - 2 * p1)
                          + sa[2 * FF + f] * (float)(DD - 2 * p2);
                (&r.x)[fi] = beta * val;
            }
            *reinterpret_cast<float4*>(out + obase + f0) = r;
        }
    }
#endif  // !HAS_TCG
}

// ---------------------------------------------------------------------------
extern "C" void kernel_launch(void* const* d_in, const int* in_sizes, int n_in,
                              void* d_out, int out_size) {
    const float* x = (const float*)d_in[0];
    const float* k = (const float*)d_in[1];
    const float* a = (const float*)d_in[2];
    float* out = (float*)d_out;

    // Deterministic per-device arch dispatch (attribute query is capture-safe,
    // not a stream op). sm_103 devices always load the exact sm_103a cubin.
    int dev = 0, major = 0, minor = 0;
    cudaGetDevice(&dev);
    cudaDeviceGetAttribute(&major, cudaDevAttrComputeCapabilityMajor, dev);
    cudaDeviceGetAttribute(&minor, cudaDevAttrComputeCapabilityMinor, dev);
    const bool tcg = (major == 10 && minor == 3);

    binarize_kernel<<<NPIX_IN / 8, 256>>>(x);
    if (tcg) {
        wpack_kernel<<<(9 * CINC * FF) / 256, 256>>>(k, a);
        beta_kernel<<<(NPIX_OUT + 255) / 256, 256>>>();
        cudaFuncSetAttribute(abc_mma4_kernel,
                             cudaFuncAttributeMaxDynamicSharedMemorySize, SMEM_TOT);
        abc_mma4_kernel<<<NCTA, NTHREADS, SMEM_TOT>>>(out);
    } else {
        kpack_kernel<<<KWORDS / 8, 256>>>(k);
        cudaFuncSetAttribute(abc_popc_kernel,
                             cudaFuncAttributeMaxDynamicSharedMemorySize, POPC_SMEM);
        abc_popc_kernel<<<296, 256, POPC_SMEM>>>(a, out);
    }
}